// round 9
// baseline (speedup 1.0000x reference)
#include <cuda_runtime.h>
#include <cuda_bf16.h>
#include <math.h>
#include <stdint.h>

#define Bdim 4
#define Sdim 2048
#define Ddim 1024
#define Hdim 16
#define HDdim 64
#define Fdim 4096
#define Mdim (Bdim * Sdim)   // 8192
#define EPS 1e-5f

#define MDsz ((size_t)Mdim * Ddim)
#define MFsz ((size_t)Mdim * Fdim)
#define DDsz ((size_t)Ddim * Ddim)
#define DFsz ((size_t)Ddim * Fdim)

// ---------------- scratch (static device arrays; allocation-free) ----------
__device__ float g_x1[MDsz];               // residual after attention
__device__ float g_b3[3 * Ddim];           // concat bias q|k|v
// qkv split blob: [qh, ql, kh, kl, vh, vl], each MDsz, layout [B,H,S,HD]
__device__ __nv_bfloat16 g_qkvs[6 * MDsz];
__device__ __nv_bfloat16 g_xn_hi[MDsz],  g_xn_lo[MDsz];
__device__ __nv_bfloat16 g_att_hi[MDsz], g_att_lo[MDsz];
__device__ __nv_bfloat16 g_xn2_hi[MDsz], g_xn2_lo[MDsz];
__device__ __nv_bfloat16 g_h_hi[MFsz],   g_h_lo[MFsz];
__device__ __nv_bfloat16 g_wqkv_hi[3*DDsz], g_wqkv_lo[3*DDsz];  // [3072,1024] K-major
__device__ __nv_bfloat16 g_wo_hi[DDsz],  g_wo_lo[DDsz];
__device__ __nv_bfloat16 g_w1_hi[DFsz],  g_w1_lo[DFsz];
__device__ __nv_bfloat16 g_w2_hi[DFsz],  g_w2_lo[DFsz];

// ---------------- PTX helpers (baseline sm_80+ only) ------------------------
__device__ __forceinline__ uint32_t smem_u32(const void* p) {
    uint32_t a;
    asm("{ .reg .u64 t; cvta.to.shared.u64 t, %1; cvt.u32.u64 %0, t; }"
        : "=r"(a) : "l"(p));
    return a;
}
#define CPA16(d, s) asm volatile("cp.async.cg.shared.global [%0], [%1], 16;" :: "r"(d), "l"(s))
#define CPCOMMIT()  asm volatile("cp.async.commit_group;" ::: "memory")
#define CPWAIT2()   asm volatile("cp.async.wait_group 2;" ::: "memory")
#define CPWAIT1()   asm volatile("cp.async.wait_group 1;" ::: "memory")
#define CPWAIT0()   asm volatile("cp.async.wait_group 0;" ::: "memory")

#define LDSM4(r0, r1, r2, r3, a) \
    asm volatile("ldmatrix.sync.aligned.m8n8.x4.shared.b16 {%0,%1,%2,%3}, [%4];" \
                 : "=r"(r0), "=r"(r1), "=r"(r2), "=r"(r3) : "r"(a))
#define LDSM4T(r0, r1, r2, r3, a) \
    asm volatile("ldmatrix.sync.aligned.m8n8.x4.trans.shared.b16 {%0,%1,%2,%3}, [%4];" \
                 : "=r"(r0), "=r"(r1), "=r"(r2), "=r"(r3) : "r"(a))
#define LDSM2(r0, r1, a) \
    asm volatile("ldmatrix.sync.aligned.m8n8.x2.shared.b16 {%0,%1}, [%2];" \
                 : "=r"(r0), "=r"(r1) : "r"(a))
#define MMA16816(c, a, b) \
    asm volatile("mma.sync.aligned.m16n8k16.row.col.f32.bf16.bf16.f32 " \
                 "{%0,%1,%2,%3}, {%4,%5,%6,%7}, {%8,%9}, {%0,%1,%2,%3};" \
                 : "+f"((c)[0]), "+f"((c)[1]), "+f"((c)[2]), "+f"((c)[3]) \
                 : "r"((a)[0]), "r"((a)[1]), "r"((a)[2]), "r"((a)[3]), \
                   "r"((b)[0]), "r"((b)[1]))

__device__ __forceinline__ void split_bf16(float v, __nv_bfloat16& hi, __nv_bfloat16& lo) {
    hi = __float2bfloat16(v);
    lo = __float2bfloat16(v - __bfloat162float(hi));
}
__device__ __forceinline__ uint32_t pack2(__nv_bfloat16 a, __nv_bfloat16 b) {
    return (uint32_t)__bfloat16_as_ushort(a) | ((uint32_t)__bfloat16_as_ushort(b) << 16);
}
__device__ __forceinline__ void packsplit(float x, float y, uint32_t& hi, uint32_t& lo) {
    __nv_bfloat16 hx, lx, hy, ly;
    split_bf16(x, hx, lx);
    split_bf16(y, hy, ly);
    hi = pack2(hx, hy);
    lo = pack2(lx, ly);
}
// fast exp2 (no MUFU): degree-5 poly + exponent bit add. x <= 0 expected.
__device__ __forceinline__ float fexp2(float x) {
    x = fmaxf(x, -80.f);
    int ni = __float2int_rn(x);
    float r = x - (float)ni;
    float p = 1.33335581e-3f;
    p = fmaf(p, r, 9.61812911e-3f);
    p = fmaf(p, r, 5.55041086e-2f);
    p = fmaf(p, r, 2.40226507e-1f);
    p = fmaf(p, r, 6.93147182e-1f);
    p = fmaf(p, r, 1.0f);
    return __int_as_float(__float_as_int(p) + (ni << 23));
}

// ===========================================================================
// LayerNorm -> bf16 hi/lo split.
// ===========================================================================
__global__ __launch_bounds__(256) void ln_split(const float* __restrict__ X,
                                                const float* __restrict__ G,
                                                const float* __restrict__ Bt,
                                                __nv_bfloat16* __restrict__ Yhi,
                                                __nv_bfloat16* __restrict__ Ylo) {
    int row = blockIdx.x, t = threadIdx.x;
    float4 v = ((const float4*)(X + (size_t)row * Ddim))[t];
    float s  = v.x + v.y + v.z + v.w;
    float ss = v.x*v.x + v.y*v.y + v.z*v.z + v.w*v.w;
    #pragma unroll
    for (int off = 16; off > 0; off >>= 1) {
        s  += __shfl_xor_sync(0xffffffffu, s,  off);
        ss += __shfl_xor_sync(0xffffffffu, ss, off);
    }
    __shared__ float rs[8], rq[8];
    int wid = t >> 5, lane = t & 31;
    if (lane == 0) { rs[wid] = s; rq[wid] = ss; }
    __syncthreads();
    float S_ = 0.f, Q_ = 0.f;
    #pragma unroll
    for (int i = 0; i < 8; i++) { S_ += rs[i]; Q_ += rq[i]; }
    float mu = S_ * (1.0f / Ddim);
    float rstd = rsqrtf(Q_ * (1.0f / Ddim) - mu * mu + EPS);
    float4 g4 = ((const float4*)G)[t];
    float4 b4 = ((const float4*)Bt)[t];
    float y[4] = {(v.x-mu)*rstd*g4.x + b4.x, (v.y-mu)*rstd*g4.y + b4.y,
                  (v.z-mu)*rstd*g4.z + b4.z, (v.w-mu)*rstd*g4.w + b4.w};
    size_t off = (size_t)row * Ddim + t * 4;
    #pragma unroll
    for (int i = 0; i < 4; i++) {
        __nv_bfloat16 hi, lo; split_bf16(y[i], hi, lo);
        Yhi[off + i] = hi; Ylo[off + i] = lo;
    }
}

// ===========================================================================
// Weight transpose + split: W[K,N] fp32 -> Whi/Wlo [N,K] bf16 (K-major).
// ===========================================================================
__global__ __launch_bounds__(256) void wsplit(const float* __restrict__ W,
                                              __nv_bfloat16* __restrict__ Whi,
                                              __nv_bfloat16* __restrict__ Wlo,
                                              int K, int N) {
    __shared__ float tile[32][33];
    int tx = threadIdx.x & 31, ty = threadIdx.x >> 5;
    int bn = blockIdx.x * 32, bk = blockIdx.y * 32;
    #pragma unroll
    for (int i = 0; i < 4; i++)
        tile[ty + i*8][tx] = W[(size_t)(bk + ty + i*8) * N + bn + tx];
    __syncthreads();
    #pragma unroll
    for (int i = 0; i < 4; i++) {
        int n = bn + ty + i*8, k = bk + tx;
        __nv_bfloat16 hi, lo; split_bf16(tile[tx][ty + i*8], hi, lo);
        Whi[(size_t)n * K + k] = hi;
        Wlo[(size_t)n * K + k] = lo;
    }
}

__global__ void bias3(const float* a, const float* b, const float* c, float* o) {
    int i = blockIdx.x * 256 + threadIdx.x;
    if (i < 3072)
        o[i] = i < 1024 ? a[i] : (i < 2048 ? b[i - 1024] : c[i - 2048]);
}

// ===========================================================================
// v1 split-bf16 GEMM (BM=BN=128, warp tile 64x32, 2-stage).  Used for
// N=1024 GEMMs (O-proj, FFN2).  MODE 1: +bias +Res -> fp32.
// ===========================================================================
#define STG_ARR 10240
#define STG_BYTES (4 * STG_ARR)
#define GEMM_SMEM (2 * STG_BYTES)

template <int MODE>
__global__ __launch_bounds__(256) void gemm_tc(
    const __nv_bfloat16* __restrict__ Ahi, const __nv_bfloat16* __restrict__ Alo,
    const __nv_bfloat16* __restrict__ Bhi, const __nv_bfloat16* __restrict__ Blo,
    const float* __restrict__ bias, const float* __restrict__ Res,
    float* __restrict__ outF, __nv_bfloat16* __restrict__ outHi,
    __nv_bfloat16* __restrict__ outLo, int Nn, int Kn) {
    extern __shared__ char smem[];
    uint32_t sb = smem_u32(smem);
    int t = threadIdx.x;
    int lane = t & 31, wid = t >> 5;
    int warp_m = wid >> 2;
    int warp_n = wid & 3;
    int bm = blockIdx.y * 128, bn = blockIdx.x * 128;
    int ktiles = Kn >> 5;

    auto prefetch = [&](int kt, int s) {
        uint32_t stg = sb + s * STG_BYTES;
        #pragma unroll
        for (int it = 0; it < 8; it++) {
            int cid = t + it * 256;
            int arr = cid >> 9;
            int rem = cid & 511;
            int row = rem >> 2, ch = rem & 3;
            uint32_t dst = stg + arr * STG_ARR + row * 80 + ch * 16;
            const __nv_bfloat16* src;
            if (arr == 0)      src = Ahi + (size_t)(bm + row) * Kn;
            else if (arr == 1) src = Alo + (size_t)(bm + row) * Kn;
            else if (arr == 2) src = Bhi + (size_t)(bn + row) * Kn;
            else               src = Blo + (size_t)(bn + row) * Kn;
            src += kt * 32 + ch * 8;
            CPA16(dst, src);
        }
        CPCOMMIT();
    };

    float acc[4][4][4];
    #pragma unroll
    for (int i = 0; i < 4; i++)
        #pragma unroll
        for (int j = 0; j < 4; j++)
            #pragma unroll
            for (int r = 0; r < 4; r++) acc[i][j][r] = 0.f;

    prefetch(0, 0);
    if (ktiles > 1) prefetch(1, 1);

    int aLr = lane & 15, aLc = lane >> 4;
    int bLr = lane & 7,  bLc = (lane >> 3) & 1;

    for (int kt = 0; kt < ktiles; kt++) {
        int s = kt & 1;
        if (kt + 1 < ktiles) { CPWAIT1(); } else { CPWAIT0(); }
        __syncthreads();
        uint32_t stg = sb + s * STG_BYTES;
        uint32_t aHiB = stg,             aLoB = stg + STG_ARR;
        uint32_t bHiB = stg + 2*STG_ARR, bLoB = stg + 3*STG_ARR;

        #pragma unroll
        for (int ks = 0; ks < 2; ks++) {
            int k0 = ks * 16;
            uint32_t ahi[4][4], alo[4][4], bhi[4][2], blo[4][2];
            #pragma unroll
            for (int mt = 0; mt < 4; mt++) {
                uint32_t off = (uint32_t)(warp_m * 64 + mt * 16 + aLr) * 80
                             + (uint32_t)(k0 + aLc * 8) * 2;
                LDSM4(ahi[mt][0], ahi[mt][1], ahi[mt][2], ahi[mt][3], aHiB + off);
                LDSM4(alo[mt][0], alo[mt][1], alo[mt][2], alo[mt][3], aLoB + off);
            }
            #pragma unroll
            for (int nt = 0; nt < 4; nt++) {
                uint32_t off = (uint32_t)(warp_n * 32 + nt * 8 + bLr) * 80
                             + (uint32_t)(k0 + bLc * 8) * 2;
                LDSM2(bhi[nt][0], bhi[nt][1], bHiB + off);
                LDSM2(blo[nt][0], blo[nt][1], bLoB + off);
            }
            #pragma unroll
            for (int mt = 0; mt < 4; mt++)
                #pragma unroll
                for (int nt = 0; nt < 4; nt++) {
                    MMA16816(acc[mt][nt], ahi[mt], bhi[nt]);
                    MMA16816(acc[mt][nt], alo[mt], bhi[nt]);
                    MMA16816(acc[mt][nt], ahi[mt], blo[nt]);
                }
        }
        __syncthreads();
        if (kt + 2 < ktiles) prefetch(kt + 2, s);
    }

    int g = lane >> 2, t4 = lane & 3;
    int m_base = bm + warp_m * 64;
    int n_base = bn + warp_n * 32;

    float bcol[4][2];
    #pragma unroll
    for (int nt = 0; nt < 4; nt++) {
        int col = n_base + nt * 8 + t4 * 2;
        bcol[nt][0] = bias[col];
        bcol[nt][1] = bias[col + 1];
    }

    #pragma unroll
    for (int mt = 0; mt < 4; mt++) {
        #pragma unroll
        for (int half = 0; half < 2; half++) {
            int m = m_base + mt * 16 + g + half * 8;
            #pragma unroll
            for (int nt = 0; nt < 4; nt++) {
                int col = n_base + nt * 8 + t4 * 2;
                float v0 = acc[mt][nt][half * 2 + 0] + bcol[nt][0];
                float v1 = acc[mt][nt][half * 2 + 1] + bcol[nt][1];
                if (MODE == 1) {
                    size_t off = (size_t)m * Nn + col;
                    float2 rr = *(const float2*)(Res + off);
                    float2 w; w.x = v0 + rr.x; w.y = v1 + rr.y;
                    *(float2*)(outF + off) = w;
                } else {
                    v0 = 0.5f * v0 * (1.f + erff(v0 * 0.70710678118654752f));
                    v1 = 0.5f * v1 * (1.f + erff(v1 * 0.70710678118654752f));
                    size_t off = (size_t)m * Nn + col;
                    __nv_bfloat16 h0, l0, h1, l1;
                    split_bf16(v0, h0, l0);
                    split_bf16(v1, h1, l1);
                    *(uint32_t*)(outHi + off) = pack2(h0, h1);
                    *(uint32_t*)(outLo + off) = pack2(l0, l1);
                }
            }
        }
    }
}

// ===========================================================================
// v2 split-bf16 GEMM: BM=128, BN=256, warp tile 64x64, 3-stage cp.async.
// 8 warps: warp_m = wid&1 (2), warp_n = wid>>1 (4).
// MODE 0: QKV -> bf16 hi/lo split blob (q scaled by 0.125*log2e)
// MODE 2: gelu(+bias) -> bf16 hi/lo
// ===========================================================================
#define STG2_A 10240                    // 128*80
#define STG2_B 20480                    // 256*80
#define STG2_BYTES (2*STG2_A + 2*STG2_B)  // 61440
#define GEMM2_SMEM (3 * STG2_BYTES)       // 184320

template <int MODE>
__global__ __launch_bounds__(256) void gemm_tc2(
    const __nv_bfloat16* __restrict__ Ahi, const __nv_bfloat16* __restrict__ Alo,
    const __nv_bfloat16* __restrict__ Bhi, const __nv_bfloat16* __restrict__ Blo,
    const float* __restrict__ bias,
    __nv_bfloat16* __restrict__ outHi, __nv_bfloat16* __restrict__ outLo,
    int Nn, int Kn) {
    extern __shared__ char smem[];
    uint32_t sb = smem_u32(smem);
    int t = threadIdx.x;
    int lane = t & 31, wid = t >> 5;
    int warp_m = wid & 1;
    int warp_n = wid >> 1;
    int bm = blockIdx.y * 128, bn = blockIdx.x * 256;
    int ktiles = Kn >> 5;

    auto prefetch = [&](int kt, int s) {
        uint32_t stg = sb + s * STG2_BYTES;
        #pragma unroll
        for (int it = 0; it < 12; it++) {
            int cid = t + it * 256;            // 0..3071
            const __nv_bfloat16* src;
            uint32_t dst;
            if (cid < 1024) {                  // A hi/lo: 512 chunks each
                int arr = cid >> 9;            // 0 Ahi, 1 Alo
                int rem = cid & 511;
                int row = rem >> 2, ch = rem & 3;
                dst = stg + arr * STG2_A + row * 80 + ch * 16;
                src = (arr ? Alo : Ahi) + (size_t)(bm + row) * Kn + kt * 32 + ch * 8;
            } else {                           // B hi/lo: 1024 chunks each
                int cb = cid - 1024;
                int arr = cb >> 10;            // 0 Bhi, 1 Blo
                int rem = cb & 1023;
                int row = rem >> 2, ch = rem & 3;
                dst = stg + 2 * STG2_A + arr * STG2_B + row * 80 + ch * 16;
                src = (arr ? Blo : Bhi) + (size_t)(bn + row) * Kn + kt * 32 + ch * 8;
            }
            CPA16(dst, src);
        }
        CPCOMMIT();
    };

    float acc[4][8][4];
    #pragma unroll
    for (int i = 0; i < 4; i++)
        #pragma unroll
        for (int j = 0; j < 8; j++)
            #pragma unroll
            for (int r = 0; r < 4; r++) acc[i][j][r] = 0.f;

    prefetch(0, 0);
    prefetch(1, 1);

    int aLr = lane & 15, aLc = lane >> 4;
    int bLr = lane & 7,  bLc = (lane >> 3) & 1;

    int s = 0;
    for (int kt = 0; kt < ktiles; kt++) {
        if (kt + 2 < ktiles) {
            prefetch(kt + 2, (kt + 2) % 3);
            CPWAIT2();
        } else if (kt + 1 < ktiles) {
            CPWAIT1();
        } else {
            CPWAIT0();
        }
        __syncthreads();
        uint32_t stg = sb + s * STG2_BYTES;
        uint32_t aHiB = stg, aLoB = stg + STG2_A;
        uint32_t bHiB = stg + 2 * STG2_A, bLoB = bHiB + STG2_B;

        #pragma unroll
        for (int ks = 0; ks < 2; ks++) {
            int k0 = ks * 16;
            uint32_t ahi[4][4], alo[4][4];
            #pragma unroll
            for (int mt = 0; mt < 4; mt++) {
                uint32_t off = (uint32_t)(warp_m * 64 + mt * 16 + aLr) * 80
                             + (uint32_t)(k0 + aLc * 8) * 2;
                LDSM4(ahi[mt][0], ahi[mt][1], ahi[mt][2], ahi[mt][3], aHiB + off);
                LDSM4(alo[mt][0], alo[mt][1], alo[mt][2], alo[mt][3], aLoB + off);
            }
            #pragma unroll
            for (int ntg = 0; ntg < 2; ntg++) {
                uint32_t bhi[4][2], blo[4][2];
                #pragma unroll
                for (int j = 0; j < 4; j++) {
                    int nt = ntg * 4 + j;
                    uint32_t off = (uint32_t)(warp_n * 64 + nt * 8 + bLr) * 80
                                 + (uint32_t)(k0 + bLc * 8) * 2;
                    LDSM2(bhi[j][0], bhi[j][1], bHiB + off);
                    LDSM2(blo[j][0], blo[j][1], bLoB + off);
                }
                #pragma unroll
                for (int mt = 0; mt < 4; mt++)
                    #pragma unroll
                    for (int j = 0; j < 4; j++) {
                        MMA16816(acc[mt][ntg * 4 + j], ahi[mt], bhi[j]);
                        MMA16816(acc[mt][ntg * 4 + j], alo[mt], bhi[j]);
                        MMA16816(acc[mt][ntg * 4 + j], ahi[mt], blo[j]);
                    }
            }
        }
        __syncthreads();
        s = (s + 1) % 3;
    }

    // ---------------- epilogue ----------------
    int g = lane >> 2, t4 = lane & 3;
    int m_base = bm + warp_m * 64;
    int n_base = bn + warp_n * 64;

    #pragma unroll
    for (int mt = 0; mt < 4; mt++) {
        #pragma unroll
        for (int half = 0; half < 2; half++) {
            int m = m_base + mt * 16 + g + half * 8;
            int b_ = m >> 11, s_ = m & 2047;
            #pragma unroll
            for (int nt = 0; nt < 8; nt++) {
                int col = n_base + nt * 8 + t4 * 2;
                float v0 = acc[mt][nt][half * 2 + 0] + bias[col];
                float v1 = acc[mt][nt][half * 2 + 1] + bias[col + 1];
                if (MODE == 0) {
                    int mat = col >> 10;                 // 0=q,1=k,2=v
                    int nn = col & 1023;
                    int h_ = nn >> 6, hd = nn & 63;
                    if (mat == 0) {                      // fold 1/8 * log2(e)
                        v0 *= 0.180336878f;
                        v1 *= 0.180336878f;
                    }
                    __nv_bfloat16 h0, l0, h1, l1;
                    split_bf16(v0, h0, l0);
                    split_bf16(v1, h1, l1);
                    __nv_bfloat16* hiA = outHi + (size_t)mat * 2 * MDsz;
                    __nv_bfloat16* loA = hiA + MDsz;
                    size_t off = ((((size_t)b_ * Hdim + h_) * Sdim + s_) << 6) + hd;
                    *(uint32_t*)(hiA + off) = pack2(h0, h1);
                    *(uint32_t*)(loA + off) = pack2(l0, l1);
                } else {
                    v0 = 0.5f * v0 * (1.f + erff(v0 * 0.70710678118654752f));
                    v1 = 0.5f * v1 * (1.f + erff(v1 * 0.70710678118654752f));
                    size_t off = (size_t)m * Nn + col;
                    __nv_bfloat16 h0, l0, h1, l1;
                    split_bf16(v0, h0, l0);
                    split_bf16(v1, h1, l1);
                    *(uint32_t*)(outHi + off) = pack2(h0, h1);
                    *(uint32_t*)(outLo + off) = pack2(l0, l1);
                }
            }
        }
    }
}

// ===========================================================================
// Tensor-core flash attention (split-bf16, base-2 softmax, FFMA exp2).
// ===========================================================================
#define SROW 144
#define AQ_BYTES (128 * SROW)
#define KV_ARR (64 * SROW)
#define KV_STG (4 * KV_ARR)
#define ATTN_SMEM (2 * AQ_BYTES + 2 * KV_STG)   // 110592

__global__ __launch_bounds__(256) void attn_tc(
    const __nv_bfloat16* __restrict__ qkvs,
    __nv_bfloat16* __restrict__ Ohi, __nv_bfloat16* __restrict__ Olo) {
    extern __shared__ char smem[];
    uint32_t sb = smem_u32(smem);
    int t = threadIdx.x;
    int lane = t & 31, wid = t >> 5;
    int g = lane >> 2, t4 = lane & 3;
    int bh = blockIdx.y;
    int b_ = bh >> 4, h_ = bh & 15;
    int q0 = blockIdx.x * 128;

    const __nv_bfloat16* Qh = qkvs + ((size_t)bh * Sdim + q0) * HDdim;
    const __nv_bfloat16* Ql = Qh + MDsz;
    const __nv_bfloat16* Kh = qkvs + 2 * MDsz + (size_t)bh * Sdim * HDdim;
    const __nv_bfloat16* Kl = Kh + MDsz;
    const __nv_bfloat16* Vh = Kh + 2 * MDsz;
    const __nv_bfloat16* Vl = Kh + 3 * MDsz;

    uint32_t QHs = sb, QLs = sb + AQ_BYTES;
    uint32_t KVs = sb + 2 * AQ_BYTES;

    #pragma unroll
    for (int it = 0; it < 8; it++) {
        int cid = t + it * 256;
        int arr = cid >> 10;
        int rem = cid & 1023;
        int row = rem >> 3, ch = rem & 7;
        uint32_t dst = (arr ? QLs : QHs) + row * SROW + ch * 16;
        const __nv_bfloat16* src = (arr ? Ql : Qh) + (size_t)row * HDdim + ch * 8;
        CPA16(dst, src);
    }
    CPCOMMIT();

    auto prefetch = [&](int kt, int s) {
        uint32_t stg = KVs + s * KV_STG;
        #pragma unroll
        for (int it = 0; it < 8; it++) {
            int cid = t + it * 256;
            int arr = cid >> 9;
            int rem = cid & 511;
            int row = rem >> 3, ch = rem & 7;
            uint32_t dst = stg + arr * KV_ARR + row * SROW + ch * 16;
            const __nv_bfloat16* src;
            if (arr == 0)      src = Kh;
            else if (arr == 1) src = Kl;
            else if (arr == 2) src = Vh;
            else               src = Vl;
            src += (size_t)(kt * 64 + row) * HDdim + ch * 8;
            CPA16(dst, src);
        }
        CPCOMMIT();
    };
    prefetch(0, 0);
    CPWAIT1();
    __syncthreads();

    uint32_t qhf[4][4], qlf[4][4];
    {
        int mrow = wid * 16;
        int aLr = lane & 15, aLc = lane >> 4;
        #pragma unroll
        for (int kc = 0; kc < 4; kc++) {
            uint32_t off = (uint32_t)(mrow + aLr) * SROW + (uint32_t)(kc * 16 + aLc * 8) * 2;
            LDSM4(qhf[kc][0], qhf[kc][1], qhf[kc][2], qhf[kc][3], QHs + off);
            LDSM4(qlf[kc][0], qlf[kc][1], qlf[kc][2], qlf[kc][3], QLs + off);
        }
    }

    float o[8][4];
    #pragma unroll
    for (int i = 0; i < 8; i++)
        #pragma unroll
        for (int j = 0; j < 4; j++) o[i][j] = 0.f;
    float m0r = -1e30f, m1r = -1e30f, l0r = 0.f, l1r = 0.f;

    const int KT = Sdim / 64;
    for (int kt = 0; kt < KT; kt++) {
        int s = kt & 1;
        if (kt + 1 < KT) { prefetch(kt + 1, s ^ 1); CPWAIT1(); }
        else             { CPWAIT0(); }
        __syncthreads();
        uint32_t stg = KVs + s * KV_STG;
        uint32_t KHb = stg, KLb = stg + KV_ARR;
        uint32_t VHb = stg + 2 * KV_ARR, VLb = stg + 3 * KV_ARR;

        float c[8][4];
        #pragma unroll
        for (int i = 0; i < 8; i++)
            #pragma unroll
            for (int j = 0; j < 4; j++) c[i][j] = 0.f;

        int kRow = (lane & 7);
        int kCol = ((lane >> 3) << 3);
        #pragma unroll
        for (int nt = 0; nt < 8; nt++) {
            uint32_t base = (uint32_t)(nt * 8 + kRow) * SROW + kCol * 2;
            uint32_t khf[8], klf[8];
            LDSM4(khf[0], khf[1], khf[2], khf[3], KHb + base);
            LDSM4(khf[4], khf[5], khf[6], khf[7], KHb + base + 64);
            LDSM4(klf[0], klf[1], klf[2], klf[3], KLb + base);
            LDSM4(klf[4], klf[5], klf[6], klf[7], KLb + base + 64);
            #pragma unroll
            for (int kc = 0; kc < 4; kc++) {
                MMA16816(c[nt], qhf[kc], &khf[kc * 2]);
                MMA16816(c[nt], qlf[kc], &khf[kc * 2]);
                MMA16816(c[nt], qhf[kc], &klf[kc * 2]);
            }
        }

        float m0 = -1e30f, m1 = -1e30f;
        #pragma unroll
        for (int nt = 0; nt < 8; nt++) {
            m0 = fmaxf(m0, fmaxf(c[nt][0], c[nt][1]));
            m1 = fmaxf(m1, fmaxf(c[nt][2], c[nt][3]));
        }
        m0 = fmaxf(m0, __shfl_xor_sync(0xffffffffu, m0, 1));
        m0 = fmaxf(m0, __shfl_xor_sync(0xffffffffu, m0, 2));
        m1 = fmaxf(m1, __shfl_xor_sync(0xffffffffu, m1, 1));
        m1 = fmaxf(m1, __shfl_xor_sync(0xffffffffu, m1, 2));
        float mn0 = fmaxf(m0r, m0), mn1 = fmaxf(m1r, m1);
        float a0 = fexp2(m0r - mn0), a1 = fexp2(m1r - mn1);
        float s0 = 0.f, s1 = 0.f;
        #pragma unroll
        for (int nt = 0; nt < 8; nt++) {
            c[nt][0] = fexp2(c[nt][0] - mn0);
            c[nt][1] = fexp2(c[nt][1] - mn0);
            c[nt][2] = fexp2(c[nt][2] - mn1);
            c[nt][3] = fexp2(c[nt][3] - mn1);
            s0 += c[nt][0] + c[nt][1];
            s1 += c[nt][2] + c[nt][3];
        }
        s0 += __shfl_xor_sync(0xffffffffu, s0, 1);
        s0 += __shfl_xor_sync(0xffffffffu, s0, 2);
        s1 += __shfl_xor_sync(0xffffffffu, s1, 1);
        s1 += __shfl_xor_sync(0xffffffffu, s1, 2);
        l0r = l0r * a0 + s0;
        l1r = l1r * a1 + s1;
        m0r = mn0; m1r = mn1;
        #pragma unroll
        for (int i = 0; i < 8; i++) {
            o[i][0] *= a0; o[i][1] *= a0;
            o[i][2] *= a1; o[i][3] *= a1;
        }

        uint32_t ph[4][4], pl[4][4];
        #pragma unroll
        for (int kc = 0; kc < 4; kc++) {
            packsplit(c[2*kc][0],   c[2*kc][1],   ph[kc][0], pl[kc][0]);
            packsplit(c[2*kc][2],   c[2*kc][3],   ph[kc][1], pl[kc][1]);
            packsplit(c[2*kc+1][0], c[2*kc+1][1], ph[kc][2], pl[kc][2]);
            packsplit(c[2*kc+1][2], c[2*kc+1][3], ph[kc][3], pl[kc][3]);
        }

        int vRow = ((lane >> 3) & 1) * 8 + (lane & 7);
        int vCol = ((lane >> 4) << 3);
        #pragma unroll
        for (int np = 0; np < 4; np++) {
            #pragma unroll
            for (int kc = 0; kc < 4; kc++) {
                uint32_t base = (uint32_t)(kc * 16 + vRow) * SROW
                              + (uint32_t)(np * 16 + vCol) * 2;
                uint32_t vhf[4], vlf[4];
                LDSM4T(vhf[0], vhf[1], vhf[2], vhf[3], VHb + base);
                LDSM4T(vlf[0], vlf[1], vlf[2], vlf[3], VLb + base);
                MMA16816(o[2*np],   ph[kc], &vhf[0]);
                MMA16816(o[2*np],   pl[kc], &vhf[0]);
                MMA16816(o[2*np],   ph[kc], &vlf[0]);
                MMA16816(o[2*np+1], ph[kc], &vhf[2]);
                MMA16816(o[2*np+1], pl[kc], &vhf[2]);
                MMA16816(o[2*np+1], ph[kc], &vlf[2]);
            }
        }
        __syncthreads();
    }

    float inv0 = 1.0f / l0r, inv1 = 1.0f / l1r;
    int r0 = q0 + wid * 16 + g, r1 = r0 + 8;
    size_t base0 = ((size_t)b_ * Sdim + r0) * Ddim + h_ * HDdim;
    size_t base1 = ((size_t)b_ * Sdim + r1) * Ddim + h_ * HDdim;
    #pragma unroll
    for (int nt = 0; nt < 8; nt++) {
        int col = nt * 8 + t4 * 2;
        __nv_bfloat16 h0, l0, h1, l1;
        split_bf16(o[nt][0] * inv0, h0, l0);
        split_bf16(o[nt][1] * inv0, h1, l1);
        *(uint32_t*)(Ohi + base0 + col) = pack2(h0, h1);
        *(uint32_t*)(Olo + base0 + col) = pack2(l0, l1);
        split_bf16(o[nt][2] * inv1, h0, l0);
        split_bf16(o[nt][3] * inv1, h1, l1);
        *(uint32_t*)(Ohi + base1 + col) = pack2(h0, h1);
        *(uint32_t*)(Olo + base1 + col) = pack2(l0, l1);
    }
}

// ===========================================================================
// Launch
// ===========================================================================
extern "C" void kernel_launch(void* const* d_in, const int* in_sizes, int n_in,
                              void* d_out, int out_size) {
    const float* x   = (const float*)d_in[0];
    const float* Wq  = (const float*)d_in[1];
    const float* bq  = (const float*)d_in[2];
    const float* Wk  = (const float*)d_in[3];
    const float* bk  = (const float*)d_in[4];
    const float* Wv  = (const float*)d_in[5];
    const float* bv  = (const float*)d_in[6];
    const float* Wo  = (const float*)d_in[7];
    const float* bo  = (const float*)d_in[8];
    const float* W1  = (const float*)d_in[9];
    const float* b1  = (const float*)d_in[10];
    const float* W2  = (const float*)d_in[11];
    const float* b2  = (const float*)d_in[12];
    const float* g1  = (const float*)d_in[13];
    const float* be1 = (const float*)d_in[14];
    const float* g2  = (const float*)d_in[15];
    const float* be2 = (const float*)d_in[16];
    float* out = (float*)d_out;

    float *x1, *b3;
    __nv_bfloat16 *qkvs, *xnh, *xnl, *ath, *atl, *xn2h, *xn2l, *hh, *hl;
    __nv_bfloat16 *wqh, *wql, *woh, *wol, *w1h, *w1l, *w2h, *w2l;
    cudaGetSymbolAddress((void**)&x1, g_x1);
    cudaGetSymbolAddress((void**)&b3, g_b3);
    cudaGetSymbolAddress((void**)&qkvs, g_qkvs);
    cudaGetSymbolAddress((void**)&xnh, g_xn_hi);
    cudaGetSymbolAddress((void**)&xnl, g_xn_lo);
    cudaGetSymbolAddress((void**)&ath, g_att_hi);
    cudaGetSymbolAddress((void**)&atl, g_att_lo);
    cudaGetSymbolAddress((void**)&xn2h, g_xn2_hi);
    cudaGetSymbolAddress((void**)&xn2l, g_xn2_lo);
    cudaGetSymbolAddress((void**)&hh, g_h_hi);
    cudaGetSymbolAddress((void**)&hl, g_h_lo);
    cudaGetSymbolAddress((void**)&wqh, g_wqkv_hi);
    cudaGetSymbolAddress((void**)&wql, g_wqkv_lo);
    cudaGetSymbolAddress((void**)&woh, g_wo_hi);
    cudaGetSymbolAddress((void**)&wol, g_wo_lo);
    cudaGetSymbolAddress((void**)&w1h, g_w1_hi);
    cudaGetSymbolAddress((void**)&w1l, g_w1_lo);
    cudaGetSymbolAddress((void**)&w2h, g_w2_hi);
    cudaGetSymbolAddress((void**)&w2l, g_w2_lo);

    cudaFuncSetAttribute(gemm_tc<1>, cudaFuncAttributeMaxDynamicSharedMemorySize, GEMM_SMEM);
    cudaFuncSetAttribute(gemm_tc2<0>, cudaFuncAttributeMaxDynamicSharedMemorySize, GEMM2_SMEM);
    cudaFuncSetAttribute(gemm_tc2<2>, cudaFuncAttributeMaxDynamicSharedMemorySize, GEMM2_SMEM);
    cudaFuncSetAttribute(attn_tc, cudaFuncAttributeMaxDynamicSharedMemorySize, ATTN_SMEM);

    dim3 blk(256);
    wsplit<<<dim3(32, 32), blk>>>(Wq, wqh, wql, Ddim, Ddim);
    wsplit<<<dim3(32, 32), blk>>>(Wk, wqh + DDsz, wql + DDsz, Ddim, Ddim);
    wsplit<<<dim3(32, 32), blk>>>(Wv, wqh + 2 * DDsz, wql + 2 * DDsz, Ddim, Ddim);
    wsplit<<<dim3(32, 32), blk>>>(Wo, woh, wol, Ddim, Ddim);
    wsplit<<<dim3(128, 32), blk>>>(W1, w1h, w1l, Ddim, Fdim);
    wsplit<<<dim3(32, 128), blk>>>(W2, w2h, w2l, Fdim, Ddim);
    bias3<<<12, blk>>>(bq, bk, bv, b3);

    ln_split<<<Mdim, blk>>>(x, g1, be1, xnh, xnl);
    gemm_tc2<0><<<dim3(12, 64), blk, GEMM2_SMEM>>>(xnh, xnl, wqh, wql, b3,
                                                   qkvs, nullptr, 3072, Ddim);
    attn_tc<<<dim3(Sdim / 128, Bdim * Hdim), blk, ATTN_SMEM>>>(qkvs, ath, atl);
    gemm_tc<1><<<dim3(8, 64), blk, GEMM_SMEM>>>(ath, atl, woh, wol, bo,
                                                x, x1, nullptr, nullptr, Ddim, Ddim);
    ln_split<<<Mdim, blk>>>(x1, g2, be2, xn2h, xn2l);
    gemm_tc2<2><<<dim3(16, 64), blk, GEMM2_SMEM>>>(xn2h, xn2l, w1h, w1l, b1,
                                                   hh, hl, Fdim, Ddim);
    gemm_tc<1><<<dim3(8, 64), blk, GEMM_SMEM>>>(hh, hl, w2h, w2l, b2,
                                                x1, out, nullptr, nullptr, Ddim, Fdim);
}

// round 10
// speedup vs baseline: 1.4390x; 1.4390x over previous
#include <cuda_runtime.h>
#include <cuda_fp16.h>
#include <math.h>
#include <stdint.h>

#define Bdim 4
#define Sdim 2048
#define Ddim 1024
#define Hdim 16
#define HDdim 64
#define Fdim 4096
#define Mdim (Bdim * Sdim)   // 8192
#define EPS 1e-5f

#define MDsz ((size_t)Mdim * Ddim)
#define MFsz ((size_t)Mdim * Fdim)
#define DDsz ((size_t)Ddim * Ddim)
#define DFsz ((size_t)Ddim * Fdim)

// ---------------- scratch (static device arrays; allocation-free) ----------
__device__ float g_x1[MDsz];               // residual after attention
__device__ float g_b3[3 * Ddim];           // concat bias q|k|v
// qkv blob: [qh, ql, kh, vh], each MDsz, layout [B,H,S,HD]
__device__ __half g_qkvs[4 * MDsz];
__device__ __half g_xn_hi[MDsz],  g_xn_lo[MDsz];
__device__ __half g_att_hi[MDsz], g_att_lo[MDsz];
__device__ __half g_xn2_hi[MDsz], g_xn2_lo[MDsz];
__device__ __half g_h_hi[MFsz],   g_h_lo[MFsz];
__device__ __half g_wqkv[3*DDsz];          // [3072,1024] K-major, fp16
__device__ __half g_wo[DDsz];
__device__ __half g_w1[DFsz];
__device__ __half g_w2[DFsz];

// ---------------- PTX helpers (baseline sm_80+ only) ------------------------
__device__ __forceinline__ uint32_t smem_u32(const void* p) {
    uint32_t a;
    asm("{ .reg .u64 t; cvta.to.shared.u64 t, %1; cvt.u32.u64 %0, t; }"
        : "=r"(a) : "l"(p));
    return a;
}
#define CPA16(d, s) asm volatile("cp.async.cg.shared.global [%0], [%1], 16;" :: "r"(d), "l"(s))
#define CPCOMMIT()  asm volatile("cp.async.commit_group;" ::: "memory")
#define CPWAIT1()   asm volatile("cp.async.wait_group 1;" ::: "memory")
#define CPWAIT0()   asm volatile("cp.async.wait_group 0;" ::: "memory")

#define LDSM4(r0, r1, r2, r3, a) \
    asm volatile("ldmatrix.sync.aligned.m8n8.x4.shared.b16 {%0,%1,%2,%3}, [%4];" \
                 : "=r"(r0), "=r"(r1), "=r"(r2), "=r"(r3) : "r"(a))
#define LDSM4T(r0, r1, r2, r3, a) \
    asm volatile("ldmatrix.sync.aligned.m8n8.x4.trans.shared.b16 {%0,%1,%2,%3}, [%4];" \
                 : "=r"(r0), "=r"(r1), "=r"(r2), "=r"(r3) : "r"(a))
#define LDSM2(r0, r1, a) \
    asm volatile("ldmatrix.sync.aligned.m8n8.x2.shared.b16 {%0,%1}, [%2];" \
                 : "=r"(r0), "=r"(r1) : "r"(a))
#define MMAF16(c, a, b) \
    asm volatile("mma.sync.aligned.m16n8k16.row.col.f32.f16.f16.f32 " \
                 "{%0,%1,%2,%3}, {%4,%5,%6,%7}, {%8,%9}, {%0,%1,%2,%3};" \
                 : "+f"((c)[0]), "+f"((c)[1]), "+f"((c)[2]), "+f"((c)[3]) \
                 : "r"((a)[0]), "r"((a)[1]), "r"((a)[2]), "r"((a)[3]), \
                   "r"((b)[0]), "r"((b)[1]))

__device__ __forceinline__ void split_h(float v, __half& hi, __half& lo) {
    hi = __float2half_rn(v);
    lo = __float2half_rn(v - __half2float(hi));
}
__device__ __forceinline__ uint32_t pack2h(__half a, __half b) {
    return (uint32_t)__half_as_ushort(a) | ((uint32_t)__half_as_ushort(b) << 16);
}
__device__ __forceinline__ void packsplit_h(float x, float y, uint32_t& hi, uint32_t& lo) {
    __half hx, lx, hy, ly;
    split_h(x, hx, lx);
    split_h(y, hy, ly);
    hi = pack2h(hx, hy);
    lo = pack2h(lx, ly);
}
// fast exp2 (no MUFU): degree-5 poly + exponent bit add. x <= 0 expected.
__device__ __forceinline__ float fexp2(float x) {
    x = fmaxf(x, -80.f);
    int ni = __float2int_rn(x);
    float r = x - (float)ni;
    float p = 1.33335581e-3f;
    p = fmaf(p, r, 9.61812911e-3f);
    p = fmaf(p, r, 5.55041086e-2f);
    p = fmaf(p, r, 2.40226507e-1f);
    p = fmaf(p, r, 6.93147182e-1f);
    p = fmaf(p, r, 1.0f);
    return __int_as_float(__float_as_int(p) + (ni << 23));
}

// ===========================================================================
// LayerNorm -> fp16 hi/lo split.
// ===========================================================================
__global__ __launch_bounds__(256) void ln_split(const float* __restrict__ X,
                                                const float* __restrict__ G,
                                                const float* __restrict__ Bt,
                                                __half* __restrict__ Yhi,
                                                __half* __restrict__ Ylo) {
    int row = blockIdx.x, t = threadIdx.x;
    float4 v = ((const float4*)(X + (size_t)row * Ddim))[t];
    float s  = v.x + v.y + v.z + v.w;
    float ss = v.x*v.x + v.y*v.y + v.z*v.z + v.w*v.w;
    #pragma unroll
    for (int off = 16; off > 0; off >>= 1) {
        s  += __shfl_xor_sync(0xffffffffu, s,  off);
        ss += __shfl_xor_sync(0xffffffffu, ss, off);
    }
    __shared__ float rs[8], rq[8];
    int wid = t >> 5, lane = t & 31;
    if (lane == 0) { rs[wid] = s; rq[wid] = ss; }
    __syncthreads();
    float S_ = 0.f, Q_ = 0.f;
    #pragma unroll
    for (int i = 0; i < 8; i++) { S_ += rs[i]; Q_ += rq[i]; }
    float mu = S_ * (1.0f / Ddim);
    float rstd = rsqrtf(Q_ * (1.0f / Ddim) - mu * mu + EPS);
    float4 g4 = ((const float4*)G)[t];
    float4 b4 = ((const float4*)Bt)[t];
    float y[4] = {(v.x-mu)*rstd*g4.x + b4.x, (v.y-mu)*rstd*g4.y + b4.y,
                  (v.z-mu)*rstd*g4.z + b4.z, (v.w-mu)*rstd*g4.w + b4.w};
    size_t off = (size_t)row * Ddim + t * 4;
    #pragma unroll
    for (int i = 0; i < 4; i++) {
        __half hi, lo; split_h(y[i], hi, lo);
        Yhi[off + i] = hi; Ylo[off + i] = lo;
    }
}

// ===========================================================================
// Weight transpose + convert: W[K,N] fp32 -> fp16 [N,K] (K-major).
// ===========================================================================
__global__ __launch_bounds__(256) void wconv(const float* __restrict__ W,
                                             __half* __restrict__ Wh,
                                             int K, int N) {
    __shared__ float tile[32][33];
    int tx = threadIdx.x & 31, ty = threadIdx.x >> 5;
    int bn = blockIdx.x * 32, bk = blockIdx.y * 32;
    #pragma unroll
    for (int i = 0; i < 4; i++)
        tile[ty + i*8][tx] = W[(size_t)(bk + ty + i*8) * N + bn + tx];
    __syncthreads();
    #pragma unroll
    for (int i = 0; i < 4; i++) {
        int n = bn + ty + i*8, k = bk + tx;
        Wh[(size_t)n * K + k] = __float2half_rn(tile[tx][ty + i*8]);
    }
}

__global__ void bias3(const float* a, const float* b, const float* c, float* o) {
    int i = blockIdx.x * 256 + threadIdx.x;
    if (i < 3072)
        o[i] = i < 1024 ? a[i] : (i < 2048 ? b[i - 1024] : c[i - 2048]);
}

// ===========================================================================
// split-fp16 2-pass GEMM on mma.sync.  C = (Ahi+Alo) @ Bhi^T, B K-major [N,K].
// BM=BN=128, BK=32, 256 thr = 8 warps (2m x 4n), warp tile 64x32, 2-stage.
// MODE 0: QKV -> fp16 blob [qh,ql,kh,vh] (q scaled by 0.125*log2e)
// MODE 1: +bias +Res -> fp32     MODE 2: gelu(+bias) -> fp16 hi/lo
// ===========================================================================
#define STG_ARR 10240                 // 128 rows * 80 B
#define STG_BYTES (3 * STG_ARR)       // Ahi, Alo, B
#define GEMM_SMEM (2 * STG_BYTES)     // 61440

template <int MODE>
__global__ __launch_bounds__(256) void gemm_tc(
    const __half* __restrict__ Ahi, const __half* __restrict__ Alo,
    const __half* __restrict__ Bh,
    const float* __restrict__ bias, const float* __restrict__ Res,
    float* __restrict__ outF, __half* __restrict__ outHi,
    __half* __restrict__ outLo, int Nn, int Kn) {
    extern __shared__ char smem[];
    uint32_t sb = smem_u32(smem);
    int t = threadIdx.x;
    int lane = t & 31, wid = t >> 5;
    int warp_m = wid >> 2;
    int warp_n = wid & 3;
    int bm = blockIdx.y * 128, bn = blockIdx.x * 128;
    int ktiles = Kn >> 5;

    auto prefetch = [&](int kt, int s) {
        uint32_t stg = sb + s * STG_BYTES;
        #pragma unroll
        for (int it = 0; it < 6; it++) {
            int cid = t + it * 256;          // 0..1535
            int arr = cid >> 9;              // 0 Ahi, 1 Alo, 2 B
            int rem = cid & 511;
            int row = rem >> 2, ch = rem & 3;
            uint32_t dst = stg + arr * STG_ARR + row * 80 + ch * 16;
            const __half* src;
            if (arr == 0)      src = Ahi + (size_t)(bm + row) * Kn;
            else if (arr == 1) src = Alo + (size_t)(bm + row) * Kn;
            else               src = Bh  + (size_t)(bn + row) * Kn;
            src += kt * 32 + ch * 8;
            CPA16(dst, src);
        }
        CPCOMMIT();
    };

    float acc[4][4][4];
    #pragma unroll
    for (int i = 0; i < 4; i++)
        #pragma unroll
        for (int j = 0; j < 4; j++)
            #pragma unroll
            for (int r = 0; r < 4; r++) acc[i][j][r] = 0.f;

    prefetch(0, 0);
    if (ktiles > 1) prefetch(1, 1);

    int aLr = lane & 15, aLc = lane >> 4;
    int bLr = lane & 7,  bLc = (lane >> 3) & 1;

    for (int kt = 0; kt < ktiles; kt++) {
        int s = kt & 1;
        if (kt + 1 < ktiles) { CPWAIT1(); } else { CPWAIT0(); }
        __syncthreads();
        uint32_t stg = sb + s * STG_BYTES;
        uint32_t aHiB = stg, aLoB = stg + STG_ARR, bB = stg + 2 * STG_ARR;

        #pragma unroll
        for (int ks = 0; ks < 2; ks++) {
            int k0 = ks * 16;
            uint32_t ahi[4][4], alo[4][4], bf[4][2];
            #pragma unroll
            for (int mt = 0; mt < 4; mt++) {
                uint32_t off = (uint32_t)(warp_m * 64 + mt * 16 + aLr) * 80
                             + (uint32_t)(k0 + aLc * 8) * 2;
                LDSM4(ahi[mt][0], ahi[mt][1], ahi[mt][2], ahi[mt][3], aHiB + off);
                LDSM4(alo[mt][0], alo[mt][1], alo[mt][2], alo[mt][3], aLoB + off);
            }
            #pragma unroll
            for (int nt = 0; nt < 4; nt++) {
                uint32_t off = (uint32_t)(warp_n * 32 + nt * 8 + bLr) * 80
                             + (uint32_t)(k0 + bLc * 8) * 2;
                LDSM2(bf[nt][0], bf[nt][1], bB + off);
            }
            #pragma unroll
            for (int mt = 0; mt < 4; mt++)
                #pragma unroll
                for (int nt = 0; nt < 4; nt++) {
                    MMAF16(acc[mt][nt], ahi[mt], bf[nt]);
                    MMAF16(acc[mt][nt], alo[mt], bf[nt]);
                }
        }
        __syncthreads();
        if (kt + 2 < ktiles) prefetch(kt + 2, s);
    }

    // ---------------- epilogue ----------------
    int g = lane >> 2, t4 = lane & 3;
    int m_base = bm + warp_m * 64;
    int n_base = bn + warp_n * 32;

    float bcol[4][2];
    #pragma unroll
    for (int nt = 0; nt < 4; nt++) {
        int col = n_base + nt * 8 + t4 * 2;
        bcol[nt][0] = bias[col];
        bcol[nt][1] = bias[col + 1];
    }

    #pragma unroll
    for (int mt = 0; mt < 4; mt++) {
        #pragma unroll
        for (int half = 0; half < 2; half++) {
            int m = m_base + mt * 16 + g + half * 8;
            int b_ = m >> 11, s_ = m & 2047;
            #pragma unroll
            for (int nt = 0; nt < 4; nt++) {
                int col = n_base + nt * 8 + t4 * 2;
                float v0 = acc[mt][nt][half * 2 + 0] + bcol[nt][0];
                float v1 = acc[mt][nt][half * 2 + 1] + bcol[nt][1];
                if (MODE == 0) {
                    int mat = col >> 10;                 // 0=q,1=k,2=v
                    int nn = col & 1023;
                    int h_ = nn >> 6, hd = nn & 63;
                    size_t off = ((((size_t)b_ * Hdim + h_) * Sdim + s_) << 6) + hd;
                    if (mat == 0) {                      // fold 1/8 * log2(e)
                        v0 *= 0.180336878f;
                        v1 *= 0.180336878f;
                        __half h0, l0, h1, l1;
                        split_h(v0, h0, l0);
                        split_h(v1, h1, l1);
                        *(uint32_t*)(outHi + off) = pack2h(h0, h1);
                        *(uint32_t*)(outHi + MDsz + off) = pack2h(l0, l1);
                    } else {                             // k,v: hi only
                        *(uint32_t*)(outHi + (size_t)(mat + 1) * MDsz + off) =
                            pack2h(__float2half_rn(v0), __float2half_rn(v1));
                    }
                } else if (MODE == 1) {
                    size_t off = (size_t)m * Nn + col;
                    float2 rr = *(const float2*)(Res + off);
                    float2 w; w.x = v0 + rr.x; w.y = v1 + rr.y;
                    *(float2*)(outF + off) = w;
                } else {
                    v0 = 0.5f * v0 * (1.f + erff(v0 * 0.70710678118654752f));
                    v1 = 0.5f * v1 * (1.f + erff(v1 * 0.70710678118654752f));
                    size_t off = (size_t)m * Nn + col;
                    __half h0, l0, h1, l1;
                    split_h(v0, h0, l0);
                    split_h(v1, h1, l1);
                    *(uint32_t*)(outHi + off) = pack2h(h0, h1);
                    *(uint32_t*)(outLo + off) = pack2h(l0, l1);
                }
            }
        }
    }
}

// ===========================================================================
// Tensor-core flash attention (fp16 2-pass, base-2 softmax, FFMA exp2).
// Grid: (S/128, B*H), 256 thr = 8 warps, each warp 16 q-rows.
// K hi-only, V hi-only; Q and P hi+lo.
// ===========================================================================
#define SROW 144
#define AQ_BYTES (128 * SROW)              // 18432 per Q array
#define KV_ARR (64 * SROW)                 // 9216 per K/V array
#define KV_STG (2 * KV_ARR)                // 18432 per stage (K + V)
#define ATTN_SMEM (2 * AQ_BYTES + 2 * KV_STG)   // 73728

__global__ __launch_bounds__(256) void attn_tc(
    const __half* __restrict__ qkvs,
    __half* __restrict__ Ohi, __half* __restrict__ Olo) {
    extern __shared__ char smem[];
    uint32_t sb = smem_u32(smem);
    int t = threadIdx.x;
    int lane = t & 31, wid = t >> 5;
    int g = lane >> 2, t4 = lane & 3;
    int bh = blockIdx.y;
    int b_ = bh >> 4, h_ = bh & 15;
    int q0 = blockIdx.x * 128;

    const __half* Qh = qkvs + ((size_t)bh * Sdim + q0) * HDdim;
    const __half* Ql = Qh + MDsz;
    const __half* Kh = qkvs + 2 * MDsz + (size_t)bh * Sdim * HDdim;
    const __half* Vh = qkvs + 3 * MDsz + (size_t)bh * Sdim * HDdim;

    uint32_t QHs = sb, QLs = sb + AQ_BYTES;
    uint32_t KVs = sb + 2 * AQ_BYTES;

    // load Q tile (128 rows x 64 fp16, hi+lo)
    #pragma unroll
    for (int it = 0; it < 8; it++) {
        int cid = t + it * 256;              // 0..2047
        int arr = cid >> 10;
        int rem = cid & 1023;
        int row = rem >> 3, ch = rem & 7;
        uint32_t dst = (arr ? QLs : QHs) + row * SROW + ch * 16;
        const __half* src = (arr ? Ql : Qh) + (size_t)row * HDdim + ch * 8;
        CPA16(dst, src);
    }
    CPCOMMIT();

    auto prefetch = [&](int kt, int s) {
        uint32_t stg = KVs + s * KV_STG;
        #pragma unroll
        for (int it = 0; it < 4; it++) {
            int cid = t + it * 256;          // 0..1023
            int arr = cid >> 9;              // 0 K, 1 V
            int rem = cid & 511;
            int row = rem >> 3, ch = rem & 7;
            uint32_t dst = stg + arr * KV_ARR + row * SROW + ch * 16;
            const __half* src = (arr ? Vh : Kh)
                              + (size_t)(kt * 64 + row) * HDdim + ch * 8;
            CPA16(dst, src);
        }
        CPCOMMIT();
    };
    prefetch(0, 0);
    CPWAIT1();               // Q done (kv0 may still be in flight)
    __syncthreads();

    // Q fragments (persistent): 4 k-chunks, hi+lo
    uint32_t qhf[4][4], qlf[4][4];
    {
        int mrow = wid * 16;
        int aLr = lane & 15, aLc = lane >> 4;
        #pragma unroll
        for (int kc = 0; kc < 4; kc++) {
            uint32_t off = (uint32_t)(mrow + aLr) * SROW + (uint32_t)(kc * 16 + aLc * 8) * 2;
            LDSM4(qhf[kc][0], qhf[kc][1], qhf[kc][2], qhf[kc][3], QHs + off);
            LDSM4(qlf[kc][0], qlf[kc][1], qlf[kc][2], qlf[kc][3], QLs + off);
        }
    }

    float o[8][4];
    #pragma unroll
    for (int i = 0; i < 8; i++)
        #pragma unroll
        for (int j = 0; j < 4; j++) o[i][j] = 0.f;
    float m0r = -1e30f, m1r = -1e30f, l0r = 0.f, l1r = 0.f;

    const int KT = Sdim / 64;    // 32
    for (int kt = 0; kt < KT; kt++) {
        int s = kt & 1;
        if (kt + 1 < KT) { prefetch(kt + 1, s ^ 1); CPWAIT1(); }
        else             { CPWAIT0(); }
        __syncthreads();
        uint32_t stg = KVs + s * KV_STG;
        uint32_t KHb = stg, VHb = stg + KV_ARR;

        // ---- scores ----
        float c[8][4];
        #pragma unroll
        for (int i = 0; i < 8; i++)
            #pragma unroll
            for (int j = 0; j < 4; j++) c[i][j] = 0.f;

        int kRow = (lane & 7);
        int kCol = ((lane >> 3) << 3);
        #pragma unroll
        for (int nt = 0; nt < 8; nt++) {
            uint32_t base = (uint32_t)(nt * 8 + kRow) * SROW + kCol * 2;
            uint32_t khf[8];
            LDSM4(khf[0], khf[1], khf[2], khf[3], KHb + base);
            LDSM4(khf[4], khf[5], khf[6], khf[7], KHb + base + 64);
            #pragma unroll
            for (int kc = 0; kc < 4; kc++) {
                MMAF16(c[nt], qhf[kc], &khf[kc * 2]);
                MMAF16(c[nt], qlf[kc], &khf[kc * 2]);
            }
        }

        // ---- online softmax (base-2) ----
        float m0 = -1e30f, m1 = -1e30f;
        #pragma unroll
        for (int nt = 0; nt < 8; nt++) {
            m0 = fmaxf(m0, fmaxf(c[nt][0], c[nt][1]));
            m1 = fmaxf(m1, fmaxf(c[nt][2], c[nt][3]));
        }
        m0 = fmaxf(m0, __shfl_xor_sync(0xffffffffu, m0, 1));
        m0 = fmaxf(m0, __shfl_xor_sync(0xffffffffu, m0, 2));
        m1 = fmaxf(m1, __shfl_xor_sync(0xffffffffu, m1, 1));
        m1 = fmaxf(m1, __shfl_xor_sync(0xffffffffu, m1, 2));
        float mn0 = fmaxf(m0r, m0), mn1 = fmaxf(m1r, m1);
        float a0 = fexp2(m0r - mn0), a1 = fexp2(m1r - mn1);
        float s0 = 0.f, s1 = 0.f;
        #pragma unroll
        for (int nt = 0; nt < 8; nt++) {
            c[nt][0] = fexp2(c[nt][0] - mn0);
            c[nt][1] = fexp2(c[nt][1] - mn0);
            c[nt][2] = fexp2(c[nt][2] - mn1);
            c[nt][3] = fexp2(c[nt][3] - mn1);
            s0 += c[nt][0] + c[nt][1];
            s1 += c[nt][2] + c[nt][3];
        }
        s0 += __shfl_xor_sync(0xffffffffu, s0, 1);
        s0 += __shfl_xor_sync(0xffffffffu, s0, 2);
        s1 += __shfl_xor_sync(0xffffffffu, s1, 1);
        s1 += __shfl_xor_sync(0xffffffffu, s1, 2);
        l0r = l0r * a0 + s0;
        l1r = l1r * a1 + s1;
        m0r = mn0; m1r = mn1;
        #pragma unroll
        for (int i = 0; i < 8; i++) {
            o[i][0] *= a0; o[i][1] *= a0;
            o[i][2] *= a1; o[i][3] *= a1;
        }

        // ---- P fragments (registers, fp16 hi/lo) ----
        uint32_t ph[4][4], pl[4][4];
        #pragma unroll
        for (int kc = 0; kc < 4; kc++) {
            packsplit_h(c[2*kc][0],   c[2*kc][1],   ph[kc][0], pl[kc][0]);
            packsplit_h(c[2*kc][2],   c[2*kc][3],   ph[kc][1], pl[kc][1]);
            packsplit_h(c[2*kc+1][0], c[2*kc+1][1], ph[kc][2], pl[kc][2]);
            packsplit_h(c[2*kc+1][2], c[2*kc+1][3], ph[kc][3], pl[kc][3]);
        }

        // ---- O += P @ V ----
        int vRow = ((lane >> 3) & 1) * 8 + (lane & 7);
        int vCol = ((lane >> 4) << 3);
        #pragma unroll
        for (int np = 0; np < 4; np++) {
            #pragma unroll
            for (int kc = 0; kc < 4; kc++) {
                uint32_t base = (uint32_t)(kc * 16 + vRow) * SROW
                              + (uint32_t)(np * 16 + vCol) * 2;
                uint32_t vhf[4];
                LDSM4T(vhf[0], vhf[1], vhf[2], vhf[3], VHb + base);
                MMAF16(o[2*np],   ph[kc], &vhf[0]);
                MMAF16(o[2*np],   pl[kc], &vhf[0]);
                MMAF16(o[2*np+1], ph[kc], &vhf[2]);
                MMAF16(o[2*np+1], pl[kc], &vhf[2]);
            }
        }
        __syncthreads();
    }

    // ---- epilogue: divide by l, write fp16 hi/lo to [B,S,D] ----
    float inv0 = 1.0f / l0r, inv1 = 1.0f / l1r;
    int r0 = q0 + wid * 16 + g, r1 = r0 + 8;
    size_t base0 = ((size_t)b_ * Sdim + r0) * Ddim + h_ * HDdim;
    size_t base1 = ((size_t)b_ * Sdim + r1) * Ddim + h_ * HDdim;
    #pragma unroll
    for (int nt = 0; nt < 8; nt++) {
        int col = nt * 8 + t4 * 2;
        __half h0, l0, h1, l1;
        split_h(o[nt][0] * inv0, h0, l0);
        split_h(o[nt][1] * inv0, h1, l1);
        *(uint32_t*)(Ohi + base0 + col) = pack2h(h0, h1);
        *(uint32_t*)(Olo + base0 + col) = pack2h(l0, l1);
        split_h(o[nt][2] * inv1, h0, l0);
        split_h(o[nt][3] * inv1, h1, l1);
        *(uint32_t*)(Ohi + base1 + col) = pack2h(h0, h1);
        *(uint32_t*)(Olo + base1 + col) = pack2h(l0, l1);
    }
}

// ===========================================================================
// Launch
// ===========================================================================
extern "C" void kernel_launch(void* const* d_in, const int* in_sizes, int n_in,
                              void* d_out, int out_size) {
    const float* x   = (const float*)d_in[0];
    const float* Wq  = (const float*)d_in[1];
    const float* bq  = (const float*)d_in[2];
    const float* Wk  = (const float*)d_in[3];
    const float* bk  = (const float*)d_in[4];
    const float* Wv  = (const float*)d_in[5];
    const float* bv  = (const float*)d_in[6];
    const float* Wo  = (const float*)d_in[7];
    const float* bo  = (const float*)d_in[8];
    const float* W1  = (const float*)d_in[9];
    const float* b1  = (const float*)d_in[10];
    const float* W2  = (const float*)d_in[11];
    const float* b2  = (const float*)d_in[12];
    const float* g1  = (const float*)d_in[13];
    const float* be1 = (const float*)d_in[14];
    const float* g2  = (const float*)d_in[15];
    const float* be2 = (const float*)d_in[16];
    float* out = (float*)d_out;

    float *x1, *b3;
    __half *qkvs, *xnh, *xnl, *ath, *atl, *xn2h, *xn2l, *hh, *hl;
    __half *wqkv, *wo, *w1, *w2;
    cudaGetSymbolAddress((void**)&x1, g_x1);
    cudaGetSymbolAddress((void**)&b3, g_b3);
    cudaGetSymbolAddress((void**)&qkvs, g_qkvs);
    cudaGetSymbolAddress((void**)&xnh, g_xn_hi);
    cudaGetSymbolAddress((void**)&xnl, g_xn_lo);
    cudaGetSymbolAddress((void**)&ath, g_att_hi);
    cudaGetSymbolAddress((void**)&atl, g_att_lo);
    cudaGetSymbolAddress((void**)&xn2h, g_xn2_hi);
    cudaGetSymbolAddress((void**)&xn2l, g_xn2_lo);
    cudaGetSymbolAddress((void**)&hh, g_h_hi);
    cudaGetSymbolAddress((void**)&hl, g_h_lo);
    cudaGetSymbolAddress((void**)&wqkv, g_wqkv);
    cudaGetSymbolAddress((void**)&wo, g_wo);
    cudaGetSymbolAddress((void**)&w1, g_w1);
    cudaGetSymbolAddress((void**)&w2, g_w2);

    cudaFuncSetAttribute(gemm_tc<0>, cudaFuncAttributeMaxDynamicSharedMemorySize, GEMM_SMEM);
    cudaFuncSetAttribute(gemm_tc<1>, cudaFuncAttributeMaxDynamicSharedMemorySize, GEMM_SMEM);
    cudaFuncSetAttribute(gemm_tc<2>, cudaFuncAttributeMaxDynamicSharedMemorySize, GEMM_SMEM);
    cudaFuncSetAttribute(attn_tc, cudaFuncAttributeMaxDynamicSharedMemorySize, ATTN_SMEM);

    dim3 blk(256);
    wconv<<<dim3(32, 32), blk>>>(Wq, wqkv, Ddim, Ddim);
    wconv<<<dim3(32, 32), blk>>>(Wk, wqkv + DDsz, Ddim, Ddim);
    wconv<<<dim3(32, 32), blk>>>(Wv, wqkv + 2 * DDsz, Ddim, Ddim);
    wconv<<<dim3(32, 32), blk>>>(Wo, wo, Ddim, Ddim);
    wconv<<<dim3(128, 32), blk>>>(W1, w1, Ddim, Fdim);
    wconv<<<dim3(32, 128), blk>>>(W2, w2, Fdim, Ddim);
    bias3<<<12, blk>>>(bq, bk, bv, b3);

    ln_split<<<Mdim, blk>>>(x, g1, be1, xnh, xnl);
    gemm_tc<0><<<dim3(24, 64), blk, GEMM_SMEM>>>(xnh, xnl, wqkv, b3,
                                                 nullptr, nullptr, qkvs, nullptr, 3072, Ddim);
    attn_tc<<<dim3(Sdim / 128, Bdim * Hdim), blk, ATTN_SMEM>>>(qkvs, ath, atl);
    gemm_tc<1><<<dim3(8, 64), blk, GEMM_SMEM>>>(ath, atl, wo, bo,
                                                x, x1, nullptr, nullptr, Ddim, Ddim);
    ln_split<<<Mdim, blk>>>(x1, g2, be2, xn2h, xn2l);
    gemm_tc<2><<<dim3(32, 64), blk, GEMM_SMEM>>>(xn2h, xn2l, w1, b1,
                                                 nullptr, nullptr, hh, hl, Fdim, Ddim);
    gemm_tc<1><<<dim3(8, 64), blk, GEMM_SMEM>>>(hh, hl, w2, b2,
                                                x1, out, nullptr, nullptr, Ddim, Fdim);
}

// round 11
// speedup vs baseline: 2.4458x; 1.6997x over previous
#include <cuda_runtime.h>
#include <cuda_fp16.h>
#include <math.h>
#include <stdint.h>

#define Bdim 4
#define Sdim 2048
#define Ddim 1024
#define Hdim 16
#define HDdim 64
#define Fdim 4096
#define Mdim (Bdim * Sdim)   // 8192
#define EPS 1e-5f

#define MDsz ((size_t)Mdim * Ddim)
#define MFsz ((size_t)Mdim * Fdim)
#define DDsz ((size_t)Ddim * Ddim)
#define DFsz ((size_t)Ddim * Fdim)

// ---------------- scratch (static device arrays; allocation-free) ----------
__device__ float g_x1[MDsz];               // residual after attention
__device__ float g_b3[3 * Ddim];           // concat bias q|k|v
// qkv blob: [qh, kh, vh], each MDsz, layout [B,H,S,HD]
__device__ __half g_qkvs[3 * MDsz];
__device__ __half g_xn[MDsz];
__device__ __half g_att[MDsz];
__device__ __half g_xn2[MDsz];
__device__ __half g_h[MFsz];
__device__ __half g_wqkv[3*DDsz];          // [3072,1024] K-major, fp16
__device__ __half g_wo[DDsz];
__device__ __half g_w1[DFsz];
__device__ __half g_w2[DFsz];

// ---------------- PTX helpers (baseline sm_80+ only) ------------------------
__device__ __forceinline__ uint32_t smem_u32(const void* p) {
    uint32_t a;
    asm("{ .reg .u64 t; cvta.to.shared.u64 t, %1; cvt.u32.u64 %0, t; }"
        : "=r"(a) : "l"(p));
    return a;
}
#define CPA16(d, s) asm volatile("cp.async.cg.shared.global [%0], [%1], 16;" :: "r"(d), "l"(s))
#define CPCOMMIT()  asm volatile("cp.async.commit_group;" ::: "memory")
#define CPWAIT1()   asm volatile("cp.async.wait_group 1;" ::: "memory")
#define CPWAIT0()   asm volatile("cp.async.wait_group 0;" ::: "memory")

#define LDSM4(r0, r1, r2, r3, a) \
    asm volatile("ldmatrix.sync.aligned.m8n8.x4.shared.b16 {%0,%1,%2,%3}, [%4];" \
                 : "=r"(r0), "=r"(r1), "=r"(r2), "=r"(r3) : "r"(a))
#define LDSM4T(r0, r1, r2, r3, a) \
    asm volatile("ldmatrix.sync.aligned.m8n8.x4.trans.shared.b16 {%0,%1,%2,%3}, [%4];" \
                 : "=r"(r0), "=r"(r1), "=r"(r2), "=r"(r3) : "r"(a))
#define LDSM2(r0, r1, a) \
    asm volatile("ldmatrix.sync.aligned.m8n8.x2.shared.b16 {%0,%1}, [%2];" \
                 : "=r"(r0), "=r"(r1) : "r"(a))
#define MMAF16(c, a, b) \
    asm volatile("mma.sync.aligned.m16n8k16.row.col.f32.f16.f16.f32 " \
                 "{%0,%1,%2,%3}, {%4,%5,%6,%7}, {%8,%9}, {%0,%1,%2,%3};" \
                 : "+f"((c)[0]), "+f"((c)[1]), "+f"((c)[2]), "+f"((c)[3]) \
                 : "r"((a)[0]), "r"((a)[1]), "r"((a)[2]), "r"((a)[3]), \
                   "r"((b)[0]), "r"((b)[1]))

__device__ __forceinline__ uint32_t pack2h(__half a, __half b) {
    return (uint32_t)__half_as_ushort(a) | ((uint32_t)__half_as_ushort(b) << 16);
}
// fast exp2 (no MUFU): degree-5 poly + exponent bit add. x <= 0 expected.
__device__ __forceinline__ float fexp2(float x) {
    x = fmaxf(x, -80.f);
    int ni = __float2int_rn(x);
    float r = x - (float)ni;
    float p = 1.33335581e-3f;
    p = fmaf(p, r, 9.61812911e-3f);
    p = fmaf(p, r, 5.55041086e-2f);
    p = fmaf(p, r, 2.40226507e-1f);
    p = fmaf(p, r, 6.93147182e-1f);
    p = fmaf(p, r, 1.0f);
    return __int_as_float(__float_as_int(p) + (ni << 23));
}

// ===========================================================================
// LayerNorm -> fp16.
// ===========================================================================
__global__ __launch_bounds__(256) void ln_h(const float* __restrict__ X,
                                            const float* __restrict__ G,
                                            const float* __restrict__ Bt,
                                            __half* __restrict__ Y) {
    int row = blockIdx.x, t = threadIdx.x;
    float4 v = ((const float4*)(X + (size_t)row * Ddim))[t];
    float s  = v.x + v.y + v.z + v.w;
    float ss = v.x*v.x + v.y*v.y + v.z*v.z + v.w*v.w;
    #pragma unroll
    for (int off = 16; off > 0; off >>= 1) {
        s  += __shfl_xor_sync(0xffffffffu, s,  off);
        ss += __shfl_xor_sync(0xffffffffu, ss, off);
    }
    __shared__ float rs[8], rq[8];
    int wid = t >> 5, lane = t & 31;
    if (lane == 0) { rs[wid] = s; rq[wid] = ss; }
    __syncthreads();
    float S_ = 0.f, Q_ = 0.f;
    #pragma unroll
    for (int i = 0; i < 8; i++) { S_ += rs[i]; Q_ += rq[i]; }
    float mu = S_ * (1.0f / Ddim);
    float rstd = rsqrtf(Q_ * (1.0f / Ddim) - mu * mu + EPS);
    float4 g4 = ((const float4*)G)[t];
    float4 b4 = ((const float4*)Bt)[t];
    size_t off = (size_t)row * Ddim + t * 4;
    uint32_t w0 = pack2h(__float2half_rn((v.x-mu)*rstd*g4.x + b4.x),
                         __float2half_rn((v.y-mu)*rstd*g4.y + b4.y));
    uint32_t w1 = pack2h(__float2half_rn((v.z-mu)*rstd*g4.z + b4.z),
                         __float2half_rn((v.w-mu)*rstd*g4.w + b4.w));
    uint2 w; w.x = w0; w.y = w1;
    *(uint2*)(Y + off) = w;
}

// ===========================================================================
// Weight transpose + convert: W[K,N] fp32 -> fp16 [N,K] (K-major).
// ===========================================================================
__global__ __launch_bounds__(256) void wconv(const float* __restrict__ W,
                                             __half* __restrict__ Wh,
                                             int K, int N) {
    __shared__ float tile[32][33];
    int tx = threadIdx.x & 31, ty = threadIdx.x >> 5;
    int bn = blockIdx.x * 32, bk = blockIdx.y * 32;
    #pragma unroll
    for (int i = 0; i < 4; i++)
        tile[ty + i*8][tx] = W[(size_t)(bk + ty + i*8) * N + bn + tx];
    __syncthreads();
    #pragma unroll
    for (int i = 0; i < 4; i++) {
        int n = bn + ty + i*8, k = bk + tx;
        Wh[(size_t)n * K + k] = __float2half_rn(tile[tx][ty + i*8]);
    }
}

__global__ void bias3(const float* a, const float* b, const float* c, float* o) {
    int i = blockIdx.x * 256 + threadIdx.x;
    if (i < 3072)
        o[i] = i < 1024 ? a[i] : (i < 2048 ? b[i - 1024] : c[i - 2048]);
}

// ===========================================================================
// fp16 single-pass GEMM on mma.sync.  C = A @ B^T, B K-major [N,K].
// BM=BN=128, BK=32, 256 thr = 8 warps (2m x 4n), warp tile 64x32, 2-stage.
// MODE 0: QKV -> fp16 blob [qh,kh,vh] (q scaled by 0.125*log2e)
// MODE 1: +bias +Res -> fp32     MODE 2: gelu(+bias) -> fp16
// ===========================================================================
#define STG_ARR 10240                 // 128 rows * 80 B
#define STG_BYTES (2 * STG_ARR)       // A, B
#define GEMM_SMEM (2 * STG_BYTES)     // 40960

template <int MODE>
__global__ __launch_bounds__(256) void gemm_tc(
    const __half* __restrict__ Ah, const __half* __restrict__ Bh,
    const float* __restrict__ bias, const float* __restrict__ Res,
    float* __restrict__ outF, __half* __restrict__ outH,
    int Nn, int Kn) {
    extern __shared__ char smem[];
    uint32_t sb = smem_u32(smem);
    int t = threadIdx.x;
    int lane = t & 31, wid = t >> 5;
    int warp_m = wid >> 2;
    int warp_n = wid & 3;
    int bm = blockIdx.y * 128, bn = blockIdx.x * 128;
    int ktiles = Kn >> 5;

    auto prefetch = [&](int kt, int s) {
        uint32_t stg = sb + s * STG_BYTES;
        #pragma unroll
        for (int it = 0; it < 4; it++) {
            int cid = t + it * 256;          // 0..1023
            int arr = cid >> 9;              // 0 A, 1 B
            int rem = cid & 511;
            int row = rem >> 2, ch = rem & 3;
            uint32_t dst = stg + arr * STG_ARR + row * 80 + ch * 16;
            const __half* src = (arr ? Bh + (size_t)(bn + row) * Kn
                                     : Ah + (size_t)(bm + row) * Kn);
            src += kt * 32 + ch * 8;
            CPA16(dst, src);
        }
        CPCOMMIT();
    };

    float acc[4][4][4];
    #pragma unroll
    for (int i = 0; i < 4; i++)
        #pragma unroll
        for (int j = 0; j < 4; j++)
            #pragma unroll
            for (int r = 0; r < 4; r++) acc[i][j][r] = 0.f;

    prefetch(0, 0);
    if (ktiles > 1) prefetch(1, 1);

    int aLr = lane & 15, aLc = lane >> 4;
    int bLr = lane & 7,  bLc = (lane >> 3) & 1;

    for (int kt = 0; kt < ktiles; kt++) {
        int s = kt & 1;
        if (kt + 1 < ktiles) { CPWAIT1(); } else { CPWAIT0(); }
        __syncthreads();
        uint32_t stg = sb + s * STG_BYTES;
        uint32_t aB = stg, bB = stg + STG_ARR;

        #pragma unroll
        for (int ks = 0; ks < 2; ks++) {
            int k0 = ks * 16;
            uint32_t af[4][4], bf[4][2];
            #pragma unroll
            for (int mt = 0; mt < 4; mt++) {
                uint32_t off = (uint32_t)(warp_m * 64 + mt * 16 + aLr) * 80
                             + (uint32_t)(k0 + aLc * 8) * 2;
                LDSM4(af[mt][0], af[mt][1], af[mt][2], af[mt][3], aB + off);
            }
            #pragma unroll
            for (int nt = 0; nt < 4; nt++) {
                uint32_t off = (uint32_t)(warp_n * 32 + nt * 8 + bLr) * 80
                             + (uint32_t)(k0 + bLc * 8) * 2;
                LDSM2(bf[nt][0], bf[nt][1], bB + off);
            }
            #pragma unroll
            for (int mt = 0; mt < 4; mt++)
                #pragma unroll
                for (int nt = 0; nt < 4; nt++)
                    MMAF16(acc[mt][nt], af[mt], bf[nt]);
        }
        __syncthreads();
        if (kt + 2 < ktiles) prefetch(kt + 2, s);
    }

    // ---------------- epilogue ----------------
    int g = lane >> 2, t4 = lane & 3;
    int m_base = bm + warp_m * 64;
    int n_base = bn + warp_n * 32;

    float bcol[4][2];
    #pragma unroll
    for (int nt = 0; nt < 4; nt++) {
        int col = n_base + nt * 8 + t4 * 2;
        bcol[nt][0] = bias[col];
        bcol[nt][1] = bias[col + 1];
    }

    #pragma unroll
    for (int mt = 0; mt < 4; mt++) {
        #pragma unroll
        for (int half = 0; half < 2; half++) {
            int m = m_base + mt * 16 + g + half * 8;
            int b_ = m >> 11, s_ = m & 2047;
            #pragma unroll
            for (int nt = 0; nt < 4; nt++) {
                int col = n_base + nt * 8 + t4 * 2;
                float v0 = acc[mt][nt][half * 2 + 0] + bcol[nt][0];
                float v1 = acc[mt][nt][half * 2 + 1] + bcol[nt][1];
                if (MODE == 0) {
                    int mat = col >> 10;                 // 0=q,1=k,2=v
                    int nn = col & 1023;
                    int h_ = nn >> 6, hd = nn & 63;
                    size_t off = ((((size_t)b_ * Hdim + h_) * Sdim + s_) << 6) + hd;
                    if (mat == 0) {                      // fold 1/8 * log2(e)
                        v0 *= 0.180336878f;
                        v1 *= 0.180336878f;
                    }
                    *(uint32_t*)(outH + (size_t)mat * MDsz + off) =
                        pack2h(__float2half_rn(v0), __float2half_rn(v1));
                } else if (MODE == 1) {
                    size_t off = (size_t)m * Nn + col;
                    float2 rr = *(const float2*)(Res + off);
                    float2 w; w.x = v0 + rr.x; w.y = v1 + rr.y;
                    *(float2*)(outF + off) = w;
                } else {
                    v0 = 0.5f * v0 * (1.f + erff(v0 * 0.70710678118654752f));
                    v1 = 0.5f * v1 * (1.f + erff(v1 * 0.70710678118654752f));
                    size_t off = (size_t)m * Nn + col;
                    *(uint32_t*)(outH + off) =
                        pack2h(__float2half_rn(v0), __float2half_rn(v1));
                }
            }
        }
    }
}

// ===========================================================================
// Tensor-core flash attention (fp16 single-pass, base-2 softmax, FFMA exp2).
// Grid: (S/128, B*H), 256 thr = 8 warps, each warp 16 q-rows.
// ===========================================================================
#define SROW 144
#define AQ_BYTES (128 * SROW)              // 18432 Q
#define KV_ARR (64 * SROW)                 // 9216 per K/V array
#define KV_STG (2 * KV_ARR)                // 18432 per stage (K + V)
#define ATTN_SMEM (AQ_BYTES + 2 * KV_STG)  // 55296

__global__ __launch_bounds__(256) void attn_tc(
    const __half* __restrict__ qkvs, __half* __restrict__ O) {
    extern __shared__ char smem[];
    uint32_t sb = smem_u32(smem);
    int t = threadIdx.x;
    int lane = t & 31, wid = t >> 5;
    int g = lane >> 2, t4 = lane & 3;
    int bh = blockIdx.y;
    int b_ = bh >> 4, h_ = bh & 15;
    int q0 = blockIdx.x * 128;

    const __half* Qh = qkvs + ((size_t)bh * Sdim + q0) * HDdim;
    const __half* Kh = qkvs + MDsz + (size_t)bh * Sdim * HDdim;
    const __half* Vh = qkvs + 2 * MDsz + (size_t)bh * Sdim * HDdim;

    uint32_t QHs = sb;
    uint32_t KVs = sb + AQ_BYTES;

    // load Q tile (128 rows x 64 fp16)
    #pragma unroll
    for (int it = 0; it < 4; it++) {
        int cid = t + it * 256;              // 0..1023
        int row = cid >> 3, ch = cid & 7;
        uint32_t dst = QHs + row * SROW + ch * 16;
        const __half* src = Qh + (size_t)row * HDdim + ch * 8;
        CPA16(dst, src);
    }
    CPCOMMIT();

    auto prefetch = [&](int kt, int s) {
        uint32_t stg = KVs + s * KV_STG;
        #pragma unroll
        for (int it = 0; it < 4; it++) {
            int cid = t + it * 256;          // 0..1023
            int arr = cid >> 9;              // 0 K, 1 V
            int rem = cid & 511;
            int row = rem >> 3, ch = rem & 7;
            uint32_t dst = stg + arr * KV_ARR + row * SROW + ch * 16;
            const __half* src = (arr ? Vh : Kh)
                              + (size_t)(kt * 64 + row) * HDdim + ch * 8;
            CPA16(dst, src);
        }
        CPCOMMIT();
    };
    prefetch(0, 0);
    CPWAIT1();               // Q done (kv0 may still be in flight)
    __syncthreads();

    // Q fragments (persistent): 4 k-chunks
    uint32_t qf[4][4];
    {
        int mrow = wid * 16;
        int aLr = lane & 15, aLc = lane >> 4;
        #pragma unroll
        for (int kc = 0; kc < 4; kc++) {
            uint32_t off = (uint32_t)(mrow + aLr) * SROW + (uint32_t)(kc * 16 + aLc * 8) * 2;
            LDSM4(qf[kc][0], qf[kc][1], qf[kc][2], qf[kc][3], QHs + off);
        }
    }

    float o[8][4];
    #pragma unroll
    for (int i = 0; i < 8; i++)
        #pragma unroll
        for (int j = 0; j < 4; j++) o[i][j] = 0.f;
    float m0r = -1e30f, m1r = -1e30f, l0r = 0.f, l1r = 0.f;

    const int KT = Sdim / 64;    // 32
    for (int kt = 0; kt < KT; kt++) {
        int s = kt & 1;
        if (kt + 1 < KT) { prefetch(kt + 1, s ^ 1); CPWAIT1(); }
        else             { CPWAIT0(); }
        __syncthreads();
        uint32_t stg = KVs + s * KV_STG;
        uint32_t KHb = stg, VHb = stg + KV_ARR;

        // ---- scores ----
        float c[8][4];
        #pragma unroll
        for (int i = 0; i < 8; i++)
            #pragma unroll
            for (int j = 0; j < 4; j++) c[i][j] = 0.f;

        int kRow = (lane & 7);
        int kCol = ((lane >> 3) << 3);
        #pragma unroll
        for (int nt = 0; nt < 8; nt++) {
            uint32_t base = (uint32_t)(nt * 8 + kRow) * SROW + kCol * 2;
            uint32_t khf[8];
            LDSM4(khf[0], khf[1], khf[2], khf[3], KHb + base);
            LDSM4(khf[4], khf[5], khf[6], khf[7], KHb + base + 64);
            #pragma unroll
            for (int kc = 0; kc < 4; kc++)
                MMAF16(c[nt], qf[kc], &khf[kc * 2]);
        }

        // ---- online softmax (base-2) ----
        float m0 = -1e30f, m1 = -1e30f;
        #pragma unroll
        for (int nt = 0; nt < 8; nt++) {
            m0 = fmaxf(m0, fmaxf(c[nt][0], c[nt][1]));
            m1 = fmaxf(m1, fmaxf(c[nt][2], c[nt][3]));
        }
        m0 = fmaxf(m0, __shfl_xor_sync(0xffffffffu, m0, 1));
        m0 = fmaxf(m0, __shfl_xor_sync(0xffffffffu, m0, 2));
        m1 = fmaxf(m1, __shfl_xor_sync(0xffffffffu, m1, 1));
        m1 = fmaxf(m1, __shfl_xor_sync(0xffffffffu, m1, 2));
        float mn0 = fmaxf(m0r, m0), mn1 = fmaxf(m1r, m1);
        float a0 = fexp2(m0r - mn0), a1 = fexp2(m1r - mn1);
        float s0 = 0.f, s1 = 0.f;
        #pragma unroll
        for (int nt = 0; nt < 8; nt++) {
            c[nt][0] = fexp2(c[nt][0] - mn0);
            c[nt][1] = fexp2(c[nt][1] - mn0);
            c[nt][2] = fexp2(c[nt][2] - mn1);
            c[nt][3] = fexp2(c[nt][3] - mn1);
            s0 += c[nt][0] + c[nt][1];
            s1 += c[nt][2] + c[nt][3];
        }
        s0 += __shfl_xor_sync(0xffffffffu, s0, 1);
        s0 += __shfl_xor_sync(0xffffffffu, s0, 2);
        s1 += __shfl_xor_sync(0xffffffffu, s1, 1);
        s1 += __shfl_xor_sync(0xffffffffu, s1, 2);
        l0r = l0r * a0 + s0;
        l1r = l1r * a1 + s1;
        m0r = mn0; m1r = mn1;
        #pragma unroll
        for (int i = 0; i < 8; i++) {
            o[i][0] *= a0; o[i][1] *= a0;
            o[i][2] *= a1; o[i][3] *= a1;
        }

        // ---- P fragments (registers, fp16) ----
        uint32_t ph[4][4];
        #pragma unroll
        for (int kc = 0; kc < 4; kc++) {
            ph[kc][0] = pack2h(__float2half_rn(c[2*kc][0]),   __float2half_rn(c[2*kc][1]));
            ph[kc][1] = pack2h(__float2half_rn(c[2*kc][2]),   __float2half_rn(c[2*kc][3]));
            ph[kc][2] = pack2h(__float2half_rn(c[2*kc+1][0]), __float2half_rn(c[2*kc+1][1]));
            ph[kc][3] = pack2h(__float2half_rn(c[2*kc+1][2]), __float2half_rn(c[2*kc+1][3]));
        }

        // ---- O += P @ V ----
        int vRow = ((lane >> 3) & 1) * 8 + (lane & 7);
        int vCol = ((lane >> 4) << 3);
        #pragma unroll
        for (int np = 0; np < 4; np++) {
            #pragma unroll
            for (int kc = 0; kc < 4; kc++) {
                uint32_t base = (uint32_t)(kc * 16 + vRow) * SROW
                              + (uint32_t)(np * 16 + vCol) * 2;
                uint32_t vhf[4];
                LDSM4T(vhf[0], vhf[1], vhf[2], vhf[3], VHb + base);
                MMAF16(o[2*np],   ph[kc], &vhf[0]);
                MMAF16(o[2*np+1], ph[kc], &vhf[2]);
            }
        }
        __syncthreads();
    }

    // ---- epilogue: divide by l, write fp16 to [B,S,D] ----
    float inv0 = 1.0f / l0r, inv1 = 1.0f / l1r;
    int r0 = q0 + wid * 16 + g, r1 = r0 + 8;
    size_t base0 = ((size_t)b_ * Sdim + r0) * Ddim + h_ * HDdim;
    size_t base1 = ((size_t)b_ * Sdim + r1) * Ddim + h_ * HDdim;
    #pragma unroll
    for (int nt = 0; nt < 8; nt++) {
        int col = nt * 8 + t4 * 2;
        *(uint32_t*)(O + base0 + col) =
            pack2h(__float2half_rn(o[nt][0] * inv0), __float2half_rn(o[nt][1] * inv0));
        *(uint32_t*)(O + base1 + col) =
            pack2h(__float2half_rn(o[nt][2] * inv1), __float2half_rn(o[nt][3] * inv1));
    }
}

// ===========================================================================
// Launch
// ===========================================================================
extern "C" void kernel_launch(void* const* d_in, const int* in_sizes, int n_in,
                              void* d_out, int out_size) {
    const float* x   = (const float*)d_in[0];
    const float* Wq  = (const float*)d_in[1];
    const float* bq  = (const float*)d_in[2];
    const float* Wk  = (const float*)d_in[3];
    const float* bk  = (const float*)d_in[4];
    const float* Wv  = (const float*)d_in[5];
    const float* bv  = (const float*)d_in[6];
    const float* Wo  = (const float*)d_in[7];
    const float* bo  = (const float*)d_in[8];
    const float* W1  = (const float*)d_in[9];
    const float* b1  = (const float*)d_in[10];
    const float* W2  = (const float*)d_in[11];
    const float* b2  = (const float*)d_in[12];
    const float* g1  = (const float*)d_in[13];
    const float* be1 = (const float*)d_in[14];
    const float* g2  = (const float*)d_in[15];
    const float* be2 = (const float*)d_in[16];
    float* out = (float*)d_out;

    float *x1, *b3;
    __half *qkvs, *xn, *att, *xn2, *h;
    __half *wqkv, *wo, *w1, *w2;
    cudaGetSymbolAddress((void**)&x1, g_x1);
    cudaGetSymbolAddress((void**)&b3, g_b3);
    cudaGetSymbolAddress((void**)&qkvs, g_qkvs);
    cudaGetSymbolAddress((void**)&xn, g_xn);
    cudaGetSymbolAddress((void**)&att, g_att);
    cudaGetSymbolAddress((void**)&xn2, g_xn2);
    cudaGetSymbolAddress((void**)&h, g_h);
    cudaGetSymbolAddress((void**)&wqkv, g_wqkv);
    cudaGetSymbolAddress((void**)&wo, g_wo);
    cudaGetSymbolAddress((void**)&w1, g_w1);
    cudaGetSymbolAddress((void**)&w2, g_w2);

    cudaFuncSetAttribute(gemm_tc<0>, cudaFuncAttributeMaxDynamicSharedMemorySize, GEMM_SMEM);
    cudaFuncSetAttribute(gemm_tc<1>, cudaFuncAttributeMaxDynamicSharedMemorySize, GEMM_SMEM);
    cudaFuncSetAttribute(gemm_tc<2>, cudaFuncAttributeMaxDynamicSharedMemorySize, GEMM_SMEM);
    cudaFuncSetAttribute(attn_tc, cudaFuncAttributeMaxDynamicSharedMemorySize, ATTN_SMEM);

    dim3 blk(256);
    wconv<<<dim3(32, 32), blk>>>(Wq, wqkv, Ddim, Ddim);
    wconv<<<dim3(32, 32), blk>>>(Wk, wqkv + DDsz, Ddim, Ddim);
    wconv<<<dim3(32, 32), blk>>>(Wv, wqkv + 2 * DDsz, Ddim, Ddim);
    wconv<<<dim3(32, 32), blk>>>(Wo, wo, Ddim, Ddim);
    wconv<<<dim3(128, 32), blk>>>(W1, w1, Ddim, Fdim);
    wconv<<<dim3(32, 128), blk>>>(W2, w2, Fdim, Ddim);
    bias3<<<12, blk>>>(bq, bk, bv, b3);

    ln_h<<<Mdim, blk>>>(x, g1, be1, xn);
    gemm_tc<0><<<dim3(24, 64), blk, GEMM_SMEM>>>(xn, wqkv, b3,
                                                 nullptr, nullptr, qkvs, 3072, Ddim);
    attn_tc<<<dim3(Sdim / 128, Bdim * Hdim), blk, ATTN_SMEM>>>(qkvs, att);
    gemm_tc<1><<<dim3(8, 64), blk, GEMM_SMEM>>>(att, wo, bo,
                                                x, x1, nullptr, Ddim, Ddim);
    ln_h<<<Mdim, blk>>>(x1, g2, be2, xn2);
    gemm_tc<2><<<dim3(32, 64), blk, GEMM_SMEM>>>(xn2, w1, b1,
                                                 nullptr, nullptr, h, Fdim, Ddim);
    gemm_tc<1><<<dim3(8, 64), blk, GEMM_SMEM>>>(h, w2, b2,
                                                x1, out, nullptr, Ddim, Fdim);
}

// round 12
// speedup vs baseline: 2.5493x; 1.0423x over previous
#include <cuda_runtime.h>
#include <cuda_fp16.h>
#include <math.h>
#include <stdint.h>

#define Bdim 4
#define Sdim 2048
#define Ddim 1024
#define Hdim 16
#define HDdim 64
#define Fdim 4096
#define Mdim (Bdim * Sdim)   // 8192
#define EPS 1e-5f

#define MDsz ((size_t)Mdim * Ddim)
#define MFsz ((size_t)Mdim * Fdim)
#define DDsz ((size_t)Ddim * Ddim)
#define DFsz ((size_t)Ddim * Fdim)

// ---------------- scratch (static device arrays; allocation-free) ----------
__device__ float g_x1[MDsz];               // residual after attention
__device__ float g_b3[3 * Ddim];           // concat bias q|k|v
// qkv blob: [qh, kh, vh], each MDsz, layout [B,H,S,HD]
__device__ __half g_qkvs[3 * MDsz];
__device__ __half g_xn[MDsz];
__device__ __half g_att[MDsz];
__device__ __half g_xn2[MDsz];
__device__ __half g_h[MFsz];
__device__ __half g_wqkv[3*DDsz];          // [3072,1024] K-major, fp16
__device__ __half g_wo[DDsz];
__device__ __half g_w1[DFsz];
__device__ __half g_w2[DFsz];

// ---------------- PTX helpers (baseline sm_80+ only) ------------------------
__device__ __forceinline__ uint32_t smem_u32(const void* p) {
    uint32_t a;
    asm("{ .reg .u64 t; cvta.to.shared.u64 t, %1; cvt.u32.u64 %0, t; }"
        : "=r"(a) : "l"(p));
    return a;
}
#define CPA16(d, s) asm volatile("cp.async.cg.shared.global [%0], [%1], 16;" :: "r"(d), "l"(s))
#define CPCOMMIT()  asm volatile("cp.async.commit_group;" ::: "memory")
#define CPWAIT1()   asm volatile("cp.async.wait_group 1;" ::: "memory")
#define CPWAIT0()   asm volatile("cp.async.wait_group 0;" ::: "memory")

#define LDSM4(r0, r1, r2, r3, a) \
    asm volatile("ldmatrix.sync.aligned.m8n8.x4.shared.b16 {%0,%1,%2,%3}, [%4];" \
                 : "=r"(r0), "=r"(r1), "=r"(r2), "=r"(r3) : "r"(a))
#define LDSM4T(r0, r1, r2, r3, a) \
    asm volatile("ldmatrix.sync.aligned.m8n8.x4.trans.shared.b16 {%0,%1,%2,%3}, [%4];" \
                 : "=r"(r0), "=r"(r1), "=r"(r2), "=r"(r3) : "r"(a))
#define LDSM2(r0, r1, a) \
    asm volatile("ldmatrix.sync.aligned.m8n8.x2.shared.b16 {%0,%1}, [%2];" \
                 : "=r"(r0), "=r"(r1) : "r"(a))
#define MMAF16(c, a, b) \
    asm volatile("mma.sync.aligned.m16n8k16.row.col.f32.f16.f16.f32 " \
                 "{%0,%1,%2,%3}, {%4,%5,%6,%7}, {%8,%9}, {%0,%1,%2,%3};" \
                 : "+f"((c)[0]), "+f"((c)[1]), "+f"((c)[2]), "+f"((c)[3]) \
                 : "r"((a)[0]), "r"((a)[1]), "r"((a)[2]), "r"((a)[3]), \
                   "r"((b)[0]), "r"((b)[1]))

__device__ __forceinline__ uint32_t pack2h(__half a, __half b) {
    return (uint32_t)__half_as_ushort(a) | ((uint32_t)__half_as_ushort(b) << 16);
}
// fast exp2 (no MUFU): degree-5 poly + exponent bit add. x <= 0 expected.
__device__ __forceinline__ float fexp2(float x) {
    x = fmaxf(x, -80.f);
    int ni = __float2int_rn(x);
    float r = x - (float)ni;
    float p = 1.33335581e-3f;
    p = fmaf(p, r, 9.61812911e-3f);
    p = fmaf(p, r, 5.55041086e-2f);
    p = fmaf(p, r, 2.40226507e-1f);
    p = fmaf(p, r, 6.93147182e-1f);
    p = fmaf(p, r, 1.0f);
    return __int_as_float(__float_as_int(p) + (ni << 23));
}

// ===========================================================================
// LayerNorm -> fp16.
// ===========================================================================
__global__ __launch_bounds__(256) void ln_h(const float* __restrict__ X,
                                            const float* __restrict__ G,
                                            const float* __restrict__ Bt,
                                            __half* __restrict__ Y) {
    int row = blockIdx.x, t = threadIdx.x;
    float4 v = ((const float4*)(X + (size_t)row * Ddim))[t];
    float s  = v.x + v.y + v.z + v.w;
    float ss = v.x*v.x + v.y*v.y + v.z*v.z + v.w*v.w;
    #pragma unroll
    for (int off = 16; off > 0; off >>= 1) {
        s  += __shfl_xor_sync(0xffffffffu, s,  off);
        ss += __shfl_xor_sync(0xffffffffu, ss, off);
    }
    __shared__ float rs[8], rq[8];
    int wid = t >> 5, lane = t & 31;
    if (lane == 0) { rs[wid] = s; rq[wid] = ss; }
    __syncthreads();
    float S_ = 0.f, Q_ = 0.f;
    #pragma unroll
    for (int i = 0; i < 8; i++) { S_ += rs[i]; Q_ += rq[i]; }
    float mu = S_ * (1.0f / Ddim);
    float rstd = rsqrtf(Q_ * (1.0f / Ddim) - mu * mu + EPS);
    float4 g4 = ((const float4*)G)[t];
    float4 b4 = ((const float4*)Bt)[t];
    size_t off = (size_t)row * Ddim + t * 4;
    uint32_t w0 = pack2h(__float2half_rn((v.x-mu)*rstd*g4.x + b4.x),
                         __float2half_rn((v.y-mu)*rstd*g4.y + b4.y));
    uint32_t w1 = pack2h(__float2half_rn((v.z-mu)*rstd*g4.z + b4.z),
                         __float2half_rn((v.w-mu)*rstd*g4.w + b4.w));
    uint2 w; w.x = w0; w.y = w1;
    *(uint2*)(Y + off) = w;
}

// ===========================================================================
// Weight transpose + convert: W[K,N] fp32 -> fp16 [N,K] (K-major).
// ===========================================================================
__global__ __launch_bounds__(256) void wconv(const float* __restrict__ W,
                                             __half* __restrict__ Wh,
                                             int K, int N) {
    __shared__ float tile[32][33];
    int tx = threadIdx.x & 31, ty = threadIdx.x >> 5;
    int bn = blockIdx.x * 32, bk = blockIdx.y * 32;
    #pragma unroll
    for (int i = 0; i < 4; i++)
        tile[ty + i*8][tx] = W[(size_t)(bk + ty + i*8) * N + bn + tx];
    __syncthreads();
    #pragma unroll
    for (int i = 0; i < 4; i++) {
        int n = bn + ty + i*8, k = bk + tx;
        Wh[(size_t)n * K + k] = __float2half_rn(tile[tx][ty + i*8]);
    }
}

__global__ void bias3(const float* a, const float* b, const float* c, float* o) {
    int i = blockIdx.x * 256 + threadIdx.x;
    if (i < 3072)
        o[i] = i < 1024 ? a[i] : (i < 2048 ? b[i - 1024] : c[i - 2048]);
}

// ===========================================================================
// fp16 single-pass GEMM on mma.sync.  C = A @ B^T, B K-major [N,K].
// BM=BN=128, BK=32, 256 thr = 8 warps (2m x 4n), warp tile 64x32, 2-stage.
// 2 CTAs/SM: epilogue/prologue of one CTA overlaps mainloop of the other.
// MODE 0: QKV -> fp16 blob [qh,kh,vh] (q scaled by 0.125*log2e)
// MODE 1: +bias +Res -> fp32     MODE 2: gelu(+bias) -> fp16
// ===========================================================================
#define STG_ARR 10240                 // 128 rows * 80 B
#define STG_BYTES (2 * STG_ARR)       // A, B
#define GEMM_SMEM (2 * STG_BYTES)     // 40960

template <int MODE>
__global__ __launch_bounds__(256, 2) void gemm_tc(
    const __half* __restrict__ Ah, const __half* __restrict__ Bh,
    const float* __restrict__ bias, const float* __restrict__ Res,
    float* __restrict__ outF, __half* __restrict__ outH,
    int Nn, int Kn) {
    extern __shared__ char smem[];
    uint32_t sb = smem_u32(smem);
    int t = threadIdx.x;
    int lane = t & 31, wid = t >> 5;
    int warp_m = wid >> 2;
    int warp_n = wid & 3;
    int bm = blockIdx.y * 128, bn = blockIdx.x * 128;
    int ktiles = Kn >> 5;

    auto prefetch = [&](int kt, int s) {
        uint32_t stg = sb + s * STG_BYTES;
        #pragma unroll
        for (int it = 0; it < 4; it++) {
            int cid = t + it * 256;          // 0..1023
            int arr = cid >> 9;              // 0 A, 1 B
            int rem = cid & 511;
            int row = rem >> 2, ch = rem & 3;
            uint32_t dst = stg + arr * STG_ARR + row * 80 + ch * 16;
            const __half* src = (arr ? Bh + (size_t)(bn + row) * Kn
                                     : Ah + (size_t)(bm + row) * Kn);
            src += kt * 32 + ch * 8;
            CPA16(dst, src);
        }
        CPCOMMIT();
    };

    float acc[4][4][4];
    #pragma unroll
    for (int i = 0; i < 4; i++)
        #pragma unroll
        for (int j = 0; j < 4; j++)
            #pragma unroll
            for (int r = 0; r < 4; r++) acc[i][j][r] = 0.f;

    prefetch(0, 0);
    if (ktiles > 1) prefetch(1, 1);

    int aLr = lane & 15, aLc = lane >> 4;
    int bLr = lane & 7,  bLc = (lane >> 3) & 1;

    for (int kt = 0; kt < ktiles; kt++) {
        int s = kt & 1;
        if (kt + 1 < ktiles) { CPWAIT1(); } else { CPWAIT0(); }
        __syncthreads();
        uint32_t stg = sb + s * STG_BYTES;
        uint32_t aB = stg, bB = stg + STG_ARR;

        #pragma unroll
        for (int ks = 0; ks < 2; ks++) {
            int k0 = ks * 16;
            uint32_t af[4][4], bf[4][2];
            #pragma unroll
            for (int mt = 0; mt < 4; mt++) {
                uint32_t off = (uint32_t)(warp_m * 64 + mt * 16 + aLr) * 80
                             + (uint32_t)(k0 + aLc * 8) * 2;
                LDSM4(af[mt][0], af[mt][1], af[mt][2], af[mt][3], aB + off);
            }
            #pragma unroll
            for (int nt = 0; nt < 4; nt++) {
                uint32_t off = (uint32_t)(warp_n * 32 + nt * 8 + bLr) * 80
                             + (uint32_t)(k0 + bLc * 8) * 2;
                LDSM2(bf[nt][0], bf[nt][1], bB + off);
            }
            #pragma unroll
            for (int mt = 0; mt < 4; mt++)
                #pragma unroll
                for (int nt = 0; nt < 4; nt++)
                    MMAF16(acc[mt][nt], af[mt], bf[nt]);
        }
        __syncthreads();
        if (kt + 2 < ktiles) prefetch(kt + 2, s);
    }

    // ---------------- epilogue ----------------
    int g = lane >> 2, t4 = lane & 3;
    int m_base = bm + warp_m * 64;
    int n_base = bn + warp_n * 32;

    float bcol[4][2];
    #pragma unroll
    for (int nt = 0; nt < 4; nt++) {
        int col = n_base + nt * 8 + t4 * 2;
        bcol[nt][0] = bias[col];
        bcol[nt][1] = bias[col + 1];
    }

    #pragma unroll
    for (int mt = 0; mt < 4; mt++) {
        #pragma unroll
        for (int half = 0; half < 2; half++) {
            int m = m_base + mt * 16 + g + half * 8;
            int b_ = m >> 11, s_ = m & 2047;
            #pragma unroll
            for (int nt = 0; nt < 4; nt++) {
                int col = n_base + nt * 8 + t4 * 2;
                float v0 = acc[mt][nt][half * 2 + 0] + bcol[nt][0];
                float v1 = acc[mt][nt][half * 2 + 1] + bcol[nt][1];
                if (MODE == 0) {
                    int mat = col >> 10;                 // 0=q,1=k,2=v
                    int nn = col & 1023;
                    int h_ = nn >> 6, hd = nn & 63;
                    size_t off = ((((size_t)b_ * Hdim + h_) * Sdim + s_) << 6) + hd;
                    if (mat == 0) {                      // fold 1/8 * log2(e)
                        v0 *= 0.180336878f;
                        v1 *= 0.180336878f;
                    }
                    *(uint32_t*)(outH + (size_t)mat * MDsz + off) =
                        pack2h(__float2half_rn(v0), __float2half_rn(v1));
                } else if (MODE == 1) {
                    size_t off = (size_t)m * Nn + col;
                    float2 rr = *(const float2*)(Res + off);
                    float2 w; w.x = v0 + rr.x; w.y = v1 + rr.y;
                    *(float2*)(outF + off) = w;
                } else {
                    v0 = 0.5f * v0 * (1.f + erff(v0 * 0.70710678118654752f));
                    v1 = 0.5f * v1 * (1.f + erff(v1 * 0.70710678118654752f));
                    size_t off = (size_t)m * Nn + col;
                    *(uint32_t*)(outH + off) =
                        pack2h(__float2half_rn(v0), __float2half_rn(v1));
                }
            }
        }
    }
}

// ===========================================================================
// Tensor-core flash attention (fp16 single-pass, base-2 softmax, FFMA exp2).
// Grid: (S/128, B*H), 256 thr = 8 warps, each warp 16 q-rows.
// 2 CTAs/SM: softmax ALU of one CTA overlaps MMA of the other.
// ===========================================================================
#define SROW 144
#define AQ_BYTES (128 * SROW)              // 18432 Q
#define KV_ARR (64 * SROW)                 // 9216 per K/V array
#define KV_STG (2 * KV_ARR)                // 18432 per stage (K + V)
#define ATTN_SMEM (AQ_BYTES + 2 * KV_STG)  // 55296

__global__ __launch_bounds__(256, 2) void attn_tc(
    const __half* __restrict__ qkvs, __half* __restrict__ O) {
    extern __shared__ char smem[];
    uint32_t sb = smem_u32(smem);
    int t = threadIdx.x;
    int lane = t & 31, wid = t >> 5;
    int g = lane >> 2, t4 = lane & 3;
    int bh = blockIdx.y;
    int b_ = bh >> 4, h_ = bh & 15;
    int q0 = blockIdx.x * 128;

    const __half* Qh = qkvs + ((size_t)bh * Sdim + q0) * HDdim;
    const __half* Kh = qkvs + MDsz + (size_t)bh * Sdim * HDdim;
    const __half* Vh = qkvs + 2 * MDsz + (size_t)bh * Sdim * HDdim;

    uint32_t QHs = sb;
    uint32_t KVs = sb + AQ_BYTES;

    // load Q tile (128 rows x 64 fp16)
    #pragma unroll
    for (int it = 0; it < 4; it++) {
        int cid = t + it * 256;              // 0..1023
        int row = cid >> 3, ch = cid & 7;
        uint32_t dst = QHs + row * SROW + ch * 16;
        const __half* src = Qh + (size_t)row * HDdim + ch * 8;
        CPA16(dst, src);
    }
    CPCOMMIT();

    auto prefetch = [&](int kt, int s) {
        uint32_t stg = KVs + s * KV_STG;
        #pragma unroll
        for (int it = 0; it < 4; it++) {
            int cid = t + it * 256;          // 0..1023
            int arr = cid >> 9;              // 0 K, 1 V
            int rem = cid & 511;
            int row = rem >> 3, ch = rem & 7;
            uint32_t dst = stg + arr * KV_ARR + row * SROW + ch * 16;
            const __half* src = (arr ? Vh : Kh)
                              + (size_t)(kt * 64 + row) * HDdim + ch * 8;
            CPA16(dst, src);
        }
        CPCOMMIT();
    };
    prefetch(0, 0);
    CPWAIT1();               // Q done (kv0 may still be in flight)
    __syncthreads();

    // Q fragments (persistent): 4 k-chunks
    uint32_t qf[4][4];
    {
        int mrow = wid * 16;
        int aLr = lane & 15, aLc = lane >> 4;
        #pragma unroll
        for (int kc = 0; kc < 4; kc++) {
            uint32_t off = (uint32_t)(mrow + aLr) * SROW + (uint32_t)(kc * 16 + aLc * 8) * 2;
            LDSM4(qf[kc][0], qf[kc][1], qf[kc][2], qf[kc][3], QHs + off);
        }
    }

    float o[8][4];
    #pragma unroll
    for (int i = 0; i < 8; i++)
        #pragma unroll
        for (int j = 0; j < 4; j++) o[i][j] = 0.f;
    float m0r = -1e30f, m1r = -1e30f, l0r = 0.f, l1r = 0.f;

    const int KT = Sdim / 64;    // 32
    for (int kt = 0; kt < KT; kt++) {
        int s = kt & 1;
        if (kt + 1 < KT) { prefetch(kt + 1, s ^ 1); CPWAIT1(); }
        else             { CPWAIT0(); }
        __syncthreads();
        uint32_t stg = KVs + s * KV_STG;
        uint32_t KHb = stg, VHb = stg + KV_ARR;

        // ---- scores ----
        float c[8][4];
        #pragma unroll
        for (int i = 0; i < 8; i++)
            #pragma unroll
            for (int j = 0; j < 4; j++) c[i][j] = 0.f;

        int kRow = (lane & 7);
        int kCol = ((lane >> 3) << 3);
        #pragma unroll
        for (int nt = 0; nt < 8; nt++) {
            uint32_t base = (uint32_t)(nt * 8 + kRow) * SROW + kCol * 2;
            uint32_t khf[8];
            LDSM4(khf[0], khf[1], khf[2], khf[3], KHb + base);
            LDSM4(khf[4], khf[5], khf[6], khf[7], KHb + base + 64);
            #pragma unroll
            for (int kc = 0; kc < 4; kc++)
                MMAF16(c[nt], qf[kc], &khf[kc * 2]);
        }

        // ---- online softmax (base-2) ----
        float m0 = -1e30f, m1 = -1e30f;
        #pragma unroll
        for (int nt = 0; nt < 8; nt++) {
            m0 = fmaxf(m0, fmaxf(c[nt][0], c[nt][1]));
            m1 = fmaxf(m1, fmaxf(c[nt][2], c[nt][3]));
        }
        m0 = fmaxf(m0, __shfl_xor_sync(0xffffffffu, m0, 1));
        m0 = fmaxf(m0, __shfl_xor_sync(0xffffffffu, m0, 2));
        m1 = fmaxf(m1, __shfl_xor_sync(0xffffffffu, m1, 1));
        m1 = fmaxf(m1, __shfl_xor_sync(0xffffffffu, m1, 2));
        float mn0 = fmaxf(m0r, m0), mn1 = fmaxf(m1r, m1);
        float a0 = fexp2(m0r - mn0), a1 = fexp2(m1r - mn1);
        float s0 = 0.f, s1 = 0.f;
        #pragma unroll
        for (int nt = 0; nt < 8; nt++) {
            c[nt][0] = fexp2(c[nt][0] - mn0);
            c[nt][1] = fexp2(c[nt][1] - mn0);
            c[nt][2] = fexp2(c[nt][2] - mn1);
            c[nt][3] = fexp2(c[nt][3] - mn1);
            s0 += c[nt][0] + c[nt][1];
            s1 += c[nt][2] + c[nt][3];
        }
        s0 += __shfl_xor_sync(0xffffffffu, s0, 1);
        s0 += __shfl_xor_sync(0xffffffffu, s0, 2);
        s1 += __shfl_xor_sync(0xffffffffu, s1, 1);
        s1 += __shfl_xor_sync(0xffffffffu, s1, 2);
        l0r = l0r * a0 + s0;
        l1r = l1r * a1 + s1;
        m0r = mn0; m1r = mn1;
        #pragma unroll
        for (int i = 0; i < 8; i++) {
            o[i][0] *= a0; o[i][1] *= a0;
            o[i][2] *= a1; o[i][3] *= a1;
        }

        // ---- P fragments (registers, fp16) ----
        uint32_t ph[4][4];
        #pragma unroll
        for (int kc = 0; kc < 4; kc++) {
            ph[kc][0] = pack2h(__float2half_rn(c[2*kc][0]),   __float2half_rn(c[2*kc][1]));
            ph[kc][1] = pack2h(__float2half_rn(c[2*kc][2]),   __float2half_rn(c[2*kc][3]));
            ph[kc][2] = pack2h(__float2half_rn(c[2*kc+1][0]), __float2half_rn(c[2*kc+1][1]));
            ph[kc][3] = pack2h(__float2half_rn(c[2*kc+1][2]), __float2half_rn(c[2*kc+1][3]));
        }

        // ---- O += P @ V ----
        int vRow = ((lane >> 3) & 1) * 8 + (lane & 7);
        int vCol = ((lane >> 4) << 3);
        #pragma unroll
        for (int np = 0; np < 4; np++) {
            #pragma unroll
            for (int kc = 0; kc < 4; kc++) {
                uint32_t base = (uint32_t)(kc * 16 + vRow) * SROW
                              + (uint32_t)(np * 16 + vCol) * 2;
                uint32_t vhf[4];
                LDSM4T(vhf[0], vhf[1], vhf[2], vhf[3], VHb + base);
                MMAF16(o[2*np],   ph[kc], &vhf[0]);
                MMAF16(o[2*np+1], ph[kc], &vhf[2]);
            }
        }
        __syncthreads();
    }

    // ---- epilogue: divide by l, write fp16 to [B,S,D] ----
    float inv0 = 1.0f / l0r, inv1 = 1.0f / l1r;
    int r0 = q0 + wid * 16 + g, r1 = r0 + 8;
    size_t base0 = ((size_t)b_ * Sdim + r0) * Ddim + h_ * HDdim;
    size_t base1 = ((size_t)b_ * Sdim + r1) * Ddim + h_ * HDdim;
    #pragma unroll
    for (int nt = 0; nt < 8; nt++) {
        int col = nt * 8 + t4 * 2;
        *(uint32_t*)(O + base0 + col) =
            pack2h(__float2half_rn(o[nt][0] * inv0), __float2half_rn(o[nt][1] * inv0));
        *(uint32_t*)(O + base1 + col) =
            pack2h(__float2half_rn(o[nt][2] * inv1), __float2half_rn(o[nt][3] * inv1));
    }
}

// ===========================================================================
// Launch
// ===========================================================================
extern "C" void kernel_launch(void* const* d_in, const int* in_sizes, int n_in,
                              void* d_out, int out_size) {
    const float* x   = (const float*)d_in[0];
    const float* Wq  = (const float*)d_in[1];
    const float* bq  = (const float*)d_in[2];
    const float* Wk  = (const float*)d_in[3];
    const float* bk  = (const float*)d_in[4];
    const float* Wv  = (const float*)d_in[5];
    const float* bv  = (const float*)d_in[6];
    const float* Wo  = (const float*)d_in[7];
    const float* bo  = (const float*)d_in[8];
    const float* W1  = (const float*)d_in[9];
    const float* b1  = (const float*)d_in[10];
    const float* W2  = (const float*)d_in[11];
    const float* b2  = (const float*)d_in[12];
    const float* g1  = (const float*)d_in[13];
    const float* be1 = (const float*)d_in[14];
    const float* g2  = (const float*)d_in[15];
    const float* be2 = (const float*)d_in[16];
    float* out = (float*)d_out;

    float *x1, *b3;
    __half *qkvs, *xn, *att, *xn2, *h;
    __half *wqkv, *wo, *w1, *w2;
    cudaGetSymbolAddress((void**)&x1, g_x1);
    cudaGetSymbolAddress((void**)&b3, g_b3);
    cudaGetSymbolAddress((void**)&qkvs, g_qkvs);
    cudaGetSymbolAddress((void**)&xn, g_xn);
    cudaGetSymbolAddress((void**)&att, g_att);
    cudaGetSymbolAddress((void**)&xn2, g_xn2);
    cudaGetSymbolAddress((void**)&h, g_h);
    cudaGetSymbolAddress((void**)&wqkv, g_wqkv);
    cudaGetSymbolAddress((void**)&wo, g_wo);
    cudaGetSymbolAddress((void**)&w1, g_w1);
    cudaGetSymbolAddress((void**)&w2, g_w2);

    cudaFuncSetAttribute(gemm_tc<0>, cudaFuncAttributeMaxDynamicSharedMemorySize, GEMM_SMEM);
    cudaFuncSetAttribute(gemm_tc<1>, cudaFuncAttributeMaxDynamicSharedMemorySize, GEMM_SMEM);
    cudaFuncSetAttribute(gemm_tc<2>, cudaFuncAttributeMaxDynamicSharedMemorySize, GEMM_SMEM);
    cudaFuncSetAttribute(attn_tc, cudaFuncAttributeMaxDynamicSharedMemorySize, ATTN_SMEM);

    dim3 blk(256);
    wconv<<<dim3(32, 32), blk>>>(Wq, wqkv, Ddim, Ddim);
    wconv<<<dim3(32, 32), blk>>>(Wk, wqkv + DDsz, Ddim, Ddim);
    wconv<<<dim3(32, 32), blk>>>(Wv, wqkv + 2 * DDsz, Ddim, Ddim);
    wconv<<<dim3(32, 32), blk>>>(Wo, wo, Ddim, Ddim);
    wconv<<<dim3(128, 32), blk>>>(W1, w1, Ddim, Fdim);
    wconv<<<dim3(32, 128), blk>>>(W2, w2, Fdim, Ddim);
    bias3<<<12, blk>>>(bq, bk, bv, b3);

    ln_h<<<Mdim, blk>>>(x, g1, be1, xn);
    gemm_tc<0><<<dim3(24, 64), blk, GEMM_SMEM>>>(xn, wqkv, b3,
                                                 nullptr, nullptr, qkvs, 3072, Ddim);
    attn_tc<<<dim3(Sdim / 128, Bdim * Hdim), blk, ATTN_SMEM>>>(qkvs, att);
    gemm_tc<1><<<dim3(8, 64), blk, GEMM_SMEM>>>(att, wo, bo,
                                                x, x1, nullptr, Ddim, Ddim);
    ln_h<<<Mdim, blk>>>(x1, g2, be2, xn2);
    gemm_tc<2><<<dim3(32, 64), blk, GEMM_SMEM>>>(xn2, w1, b1,
                                                 nullptr, nullptr, h, Fdim, Ddim);
    gemm_tc<1><<<dim3(8, 64), blk, GEMM_SMEM>>>(h, w2, b2,
                                                x1, out, nullptr, Ddim, Fdim);
}

// round 15
// speedup vs baseline: 2.6922x; 1.0560x over previous
#include <cuda_runtime.h>
#include <cuda_fp16.h>
#include <math.h>
#include <stdint.h>

#define Bdim 4
#define Sdim 2048
#define Ddim 1024
#define Hdim 16
#define HDdim 64
#define Fdim 4096
#define Mdim (Bdim * Sdim)   // 8192
#define EPS 1e-5f

#define MDsz ((size_t)Mdim * Ddim)
#define MFsz ((size_t)Mdim * Fdim)
#define DDsz ((size_t)Ddim * Ddim)
#define DFsz ((size_t)Ddim * Fdim)

// ---------------- scratch (static device arrays; allocation-free) ----------
__device__ float g_x1[MDsz];               // residual after attention
__device__ float g_b3[3 * Ddim];           // concat bias q|k|v
// qkv blob: [qh, kh, vh], each MDsz, layout [B,H,S,HD]
__device__ __half g_qkvs[3 * MDsz];
__device__ __half g_xn[MDsz];
__device__ __half g_att[MDsz];
__device__ __half g_xn2[MDsz];
__device__ __half g_h[MFsz];
__device__ __half g_wqkv[3*DDsz];          // [3072,1024] K-major, fp16
__device__ __half g_wo[DDsz];
__device__ __half g_w1[DFsz];
__device__ __half g_w2[DFsz];

// ---------------- PTX helpers (baseline sm_80+ only) ------------------------
__device__ __forceinline__ uint32_t smem_u32(const void* p) {
    uint32_t a;
    asm("{ .reg .u64 t; cvta.to.shared.u64 t, %1; cvt.u32.u64 %0, t; }"
        : "=r"(a) : "l"(p));
    return a;
}
#define CPA16(d, s) asm volatile("cp.async.cg.shared.global [%0], [%1], 16;" :: "r"(d), "l"(s))
#define CPCOMMIT()  asm volatile("cp.async.commit_group;" ::: "memory")
#define CPWAIT2()   asm volatile("cp.async.wait_group 2;" ::: "memory")
#define CPWAIT1()   asm volatile("cp.async.wait_group 1;" ::: "memory")
#define CPWAIT0()   asm volatile("cp.async.wait_group 0;" ::: "memory")

#define LDSM4(r0, r1, r2, r3, a) \
    asm volatile("ldmatrix.sync.aligned.m8n8.x4.shared.b16 {%0,%1,%2,%3}, [%4];" \
                 : "=r"(r0), "=r"(r1), "=r"(r2), "=r"(r3) : "r"(a))
#define LDSM4T(r0, r1, r2, r3, a) \
    asm volatile("ldmatrix.sync.aligned.m8n8.x4.trans.shared.b16 {%0,%1,%2,%3}, [%4];" \
                 : "=r"(r0), "=r"(r1), "=r"(r2), "=r"(r3) : "r"(a))
#define LDSM2(r0, r1, a) \
    asm volatile("ldmatrix.sync.aligned.m8n8.x2.shared.b16 {%0,%1}, [%2];" \
                 : "=r"(r0), "=r"(r1) : "r"(a))
#define MMAF16(c, a, b) \
    asm volatile("mma.sync.aligned.m16n8k16.row.col.f32.f16.f16.f32 " \
                 "{%0,%1,%2,%3}, {%4,%5,%6,%7}, {%8,%9}, {%0,%1,%2,%3};" \
                 : "+f"((c)[0]), "+f"((c)[1]), "+f"((c)[2]), "+f"((c)[3]) \
                 : "r"((a)[0]), "r"((a)[1]), "r"((a)[2]), "r"((a)[3]), \
                   "r"((b)[0]), "r"((b)[1]))

__device__ __forceinline__ uint32_t pack2h(__half a, __half b) {
    return (uint32_t)__half_as_ushort(a) | ((uint32_t)__half_as_ushort(b) << 16);
}
// fast exp2 (no MUFU): degree-5 poly + exponent bit add. x <= 0 expected.
__device__ __forceinline__ float fexp2(float x) {
    x = fmaxf(x, -80.f);
    int ni = __float2int_rn(x);
    float r = x - (float)ni;
    float p = 1.33335581e-3f;
    p = fmaf(p, r, 9.61812911e-3f);
    p = fmaf(p, r, 5.55041086e-2f);
    p = fmaf(p, r, 2.40226507e-1f);
    p = fmaf(p, r, 6.93147182e-1f);
    p = fmaf(p, r, 1.0f);
    return __int_as_float(__float_as_int(p) + (ni << 23));
}

// ===========================================================================
// LayerNorm -> fp16.
// ===========================================================================
__global__ __launch_bounds__(256) void ln_h(const float* __restrict__ X,
                                            const float* __restrict__ G,
                                            const float* __restrict__ Bt,
                                            __half* __restrict__ Y) {
    int row = blockIdx.x, t = threadIdx.x;
    float4 v = ((const float4*)(X + (size_t)row * Ddim))[t];
    float s  = v.x + v.y + v.z + v.w;
    float ss = v.x*v.x + v.y*v.y + v.z*v.z + v.w*v.w;
    #pragma unroll
    for (int off = 16; off > 0; off >>= 1) {
        s  += __shfl_xor_sync(0xffffffffu, s,  off);
        ss += __shfl_xor_sync(0xffffffffu, ss, off);
    }
    __shared__ float rs[8], rq[8];
    int wid = t >> 5, lane = t & 31;
    if (lane == 0) { rs[wid] = s; rq[wid] = ss; }
    __syncthreads();
    float S_ = 0.f, Q_ = 0.f;
    #pragma unroll
    for (int i = 0; i < 8; i++) { S_ += rs[i]; Q_ += rq[i]; }
    float mu = S_ * (1.0f / Ddim);
    float rstd = rsqrtf(Q_ * (1.0f / Ddim) - mu * mu + EPS);
    float4 g4 = ((const float4*)G)[t];
    float4 b4 = ((const float4*)Bt)[t];
    size_t off = (size_t)row * Ddim + t * 4;
    uint32_t w0 = pack2h(__float2half_rn((v.x-mu)*rstd*g4.x + b4.x),
                         __float2half_rn((v.y-mu)*rstd*g4.y + b4.y));
    uint32_t w1 = pack2h(__float2half_rn((v.z-mu)*rstd*g4.z + b4.z),
                         __float2half_rn((v.w-mu)*rstd*g4.w + b4.w));
    uint2 w; w.x = w0; w.y = w1;
    *(uint2*)(Y + off) = w;
}

// ===========================================================================
// Fused prep: all 6 weight transpose+converts + bias concat, one launch.
// Blocks 0..4095: Wq/Wk/Wv/Wo (1024x1024, 1024 blocks each)
// Blocks 4096..8191: W1 (K=1024, N=4096)
// Blocks 8192..12287: W2 (K=4096, N=1024)
// Blocks 12288..12299: bias3
// ===========================================================================
__global__ __launch_bounds__(256) void prep_all(
    const float* __restrict__ Wq, const float* __restrict__ Wk,
    const float* __restrict__ Wv, const float* __restrict__ Wo,
    const float* __restrict__ W1, const float* __restrict__ W2,
    const float* __restrict__ bq, const float* __restrict__ bk,
    const float* __restrict__ bv,
    __half* __restrict__ wqkv, __half* __restrict__ wo,
    __half* __restrict__ w1, __half* __restrict__ w2,
    float* __restrict__ b3) {
    int id = blockIdx.x;
    if (id >= 12288) {
        int i = (id - 12288) * 256 + threadIdx.x;
        if (i < 3072)
            b3[i] = i < 1024 ? bq[i] : (i < 2048 ? bk[i - 1024] : bv[i - 2048]);
        return;
    }
    const float* W; __half* Wh; int K, N, l;
    if (id < 4096) {
        int w = id >> 10; l = id & 1023;
        K = 1024; N = 1024;
        W  = (w == 0) ? Wq : (w == 1) ? Wk : (w == 2) ? Wv : Wo;
        Wh = (w == 0) ? wqkv : (w == 1) ? wqkv + DDsz
           : (w == 2) ? wqkv + 2 * DDsz : wo;
    } else if (id < 8192) {
        l = id - 4096; K = 1024; N = 4096; W = W1; Wh = w1;
    } else {
        l = id - 8192; K = 4096; N = 1024; W = W2; Wh = w2;
    }
    int nb = N >> 5;
    int bn = (l % nb) * 32, bk_ = (l / nb) * 32;

    __shared__ float tile[32][33];
    int tx = threadIdx.x & 31, ty = threadIdx.x >> 5;
    #pragma unroll
    for (int i = 0; i < 4; i++)
        tile[ty + i*8][tx] = W[(size_t)(bk_ + ty + i*8) * N + bn + tx];
    __syncthreads();
    #pragma unroll
    for (int i = 0; i < 4; i++) {
        int n = bn + ty + i*8, k = bk_ + tx;
        Wh[(size_t)n * K + k] = __float2half_rn(tile[tx][ty + i*8]);
    }
}

// ===========================================================================
// fp16 single-pass GEMM on mma.sync.  C = A @ B^T, B K-major [N,K].
// BM=BN=128, BK=32, 256 thr = 8 warps (2m x 4n), warp tile 64x32, 3-stage,
// 2 CTAs/SM.
// MODE 0: QKV -> fp16 blob [qh,kh,vh] (q scaled by 0.125*log2e)
// MODE 1: +bias +Res -> fp32     MODE 2: gelu(+bias) -> fp16
// ===========================================================================
#define STG_ARR 10240                 // 128 rows * 80 B
#define STG_BYTES (2 * STG_ARR)       // A, B
#define GEMM_SMEM (3 * STG_BYTES)     // 61440

template <int MODE>
__global__ __launch_bounds__(256, 2) void gemm_tc(
    const __half* __restrict__ Ah, const __half* __restrict__ Bh,
    const float* __restrict__ bias, const float* __restrict__ Res,
    float* __restrict__ outF, __half* __restrict__ outH,
    int Nn, int Kn) {
    extern __shared__ char smem[];
    uint32_t sb = smem_u32(smem);
    int t = threadIdx.x;
    int lane = t & 31, wid = t >> 5;
    int warp_m = wid >> 2;
    int warp_n = wid & 3;
    int bm = blockIdx.y * 128, bn = blockIdx.x * 128;
    int ktiles = Kn >> 5;

    auto prefetch = [&](int kt, int s) {
        uint32_t stg = sb + s * STG_BYTES;
        #pragma unroll
        for (int it = 0; it < 4; it++) {
            int cid = t + it * 256;          // 0..1023
            int arr = cid >> 9;              // 0 A, 1 B
            int rem = cid & 511;
            int row = rem >> 2, ch = rem & 3;
            uint32_t dst = stg + arr * STG_ARR + row * 80 + ch * 16;
            const __half* src = (arr ? Bh + (size_t)(bn + row) * Kn
                                     : Ah + (size_t)(bm + row) * Kn);
            src += kt * 32 + ch * 8;
            CPA16(dst, src);
        }
        CPCOMMIT();
    };

    float acc[4][4][4];
    #pragma unroll
    for (int i = 0; i < 4; i++)
        #pragma unroll
        for (int j = 0; j < 4; j++)
            #pragma unroll
            for (int r = 0; r < 4; r++) acc[i][j][r] = 0.f;

    prefetch(0, 0);
    prefetch(1, 1);

    int aLr = lane & 15, aLc = lane >> 4;
    int bLr = lane & 7,  bLc = (lane >> 3) & 1;

    for (int kt = 0; kt < ktiles; kt++) {
        if (kt + 2 < ktiles) { prefetch(kt + 2, (kt + 2) % 3); CPWAIT2(); }
        else if (kt + 1 < ktiles) { CPWAIT1(); }
        else { CPWAIT0(); }
        __syncthreads();
        uint32_t stg = sb + (kt % 3) * STG_BYTES;
        uint32_t aB = stg, bB = stg + STG_ARR;

        #pragma unroll
        for (int ks = 0; ks < 2; ks++) {
            int k0 = ks * 16;
            uint32_t af[4][4], bf[4][2];
            #pragma unroll
            for (int mt = 0; mt < 4; mt++) {
                uint32_t off = (uint32_t)(warp_m * 64 + mt * 16 + aLr) * 80
                             + (uint32_t)(k0 + aLc * 8) * 2;
                LDSM4(af[mt][0], af[mt][1], af[mt][2], af[mt][3], aB + off);
            }
            #pragma unroll
            for (int nt = 0; nt < 4; nt++) {
                uint32_t off = (uint32_t)(warp_n * 32 + nt * 8 + bLr) * 80
                             + (uint32_t)(k0 + bLc * 8) * 2;
                LDSM2(bf[nt][0], bf[nt][1], bB + off);
            }
            #pragma unroll
            for (int mt = 0; mt < 4; mt++)
                #pragma unroll
                for (int nt = 0; nt < 4; nt++)
                    MMAF16(acc[mt][nt], af[mt], bf[nt]);
        }
        __syncthreads();
    }

    // ---------------- epilogue ----------------
    int g = lane >> 2, t4 = lane & 3;
    int m_base = bm + warp_m * 64;
    int n_base = bn + warp_n * 32;

    float bcol[4][2];
    #pragma unroll
    for (int nt = 0; nt < 4; nt++) {
        int col = n_base + nt * 8 + t4 * 2;
        bcol[nt][0] = bias[col];
        bcol[nt][1] = bias[col + 1];
    }

    #pragma unroll
    for (int mt = 0; mt < 4; mt++) {
        #pragma unroll
        for (int half = 0; half < 2; half++) {
            int m = m_base + mt * 16 + g + half * 8;
            int b_ = m >> 11, s_ = m & 2047;
            #pragma unroll
            for (int nt = 0; nt < 4; nt++) {
                int col = n_base + nt * 8 + t4 * 2;
                float v0 = acc[mt][nt][half * 2 + 0] + bcol[nt][0];
                float v1 = acc[mt][nt][half * 2 + 1] + bcol[nt][1];
                if (MODE == 0) {
                    int mat = col >> 10;                 // 0=q,1=k,2=v
                    int nn = col & 1023;
                    int h_ = nn >> 6, hd = nn & 63;
                    size_t off = ((((size_t)b_ * Hdim + h_) * Sdim + s_) << 6) + hd;
                    if (mat == 0) {                      // fold 1/8 * log2(e)
                        v0 *= 0.180336878f;
                        v1 *= 0.180336878f;
                    }
                    *(uint32_t*)(outH + (size_t)mat * MDsz + off) =
                        pack2h(__float2half_rn(v0), __float2half_rn(v1));
                } else if (MODE == 1) {
                    size_t off = (size_t)m * Nn + col;
                    float2 rr = *(const float2*)(Res + off);
                    float2 w; w.x = v0 + rr.x; w.y = v1 + rr.y;
                    *(float2*)(outF + off) = w;
                } else {
                    v0 = 0.5f * v0 * (1.f + erff(v0 * 0.70710678118654752f));
                    v1 = 0.5f * v1 * (1.f + erff(v1 * 0.70710678118654752f));
                    size_t off = (size_t)m * Nn + col;
                    *(uint32_t*)(outH + off) =
                        pack2h(__float2half_rn(v0), __float2half_rn(v1));
                }
            }
        }
    }
}

// ===========================================================================
// Tensor-core flash attention (fp16 single-pass, base-2 softmax, FFMA exp2).
// Grid: (S/128, B*H), 256 thr = 8 warps, each warp 16 q-rows.
// 3-stage KV pipeline, 2 CTAs/SM.
// ===========================================================================
#define SROW 144
#define AQ_BYTES (128 * SROW)              // 18432 Q
#define KV_ARR (64 * SROW)                 // 9216 per K/V array
#define KV_STG (2 * KV_ARR)                // 18432 per stage (K + V)
#define ATTN_SMEM (AQ_BYTES + 3 * KV_STG)  // 73728

__global__ __launch_bounds__(256, 2) void attn_tc(
    const __half* __restrict__ qkvs, __half* __restrict__ O) {
    extern __shared__ char smem[];
    uint32_t sb = smem_u32(smem);
    int t = threadIdx.x;
    int lane = t & 31, wid = t >> 5;
    int g = lane >> 2, t4 = lane & 3;
    int bh = blockIdx.y;
    int b_ = bh >> 4, h_ = bh & 15;
    int q0 = blockIdx.x * 128;

    const __half* Qh = qkvs + ((size_t)bh * Sdim + q0) * HDdim;
    const __half* Kh = qkvs + MDsz + (size_t)bh * Sdim * HDdim;
    const __half* Vh = qkvs + 2 * MDsz + (size_t)bh * Sdim * HDdim;

    uint32_t QHs = sb;
    uint32_t KVs = sb + AQ_BYTES;

    // load Q tile (128 rows x 64 fp16)
    #pragma unroll
    for (int it = 0; it < 4; it++) {
        int cid = t + it * 256;              // 0..1023
        int row = cid >> 3, ch = cid & 7;
        uint32_t dst = QHs + row * SROW + ch * 16;
        const __half* src = Qh + (size_t)row * HDdim + ch * 8;
        CPA16(dst, src);
    }
    CPCOMMIT();

    auto prefetch = [&](int kt, int s) {
        uint32_t stg = KVs + s * KV_STG;
        #pragma unroll
        for (int it = 0; it < 4; it++) {
            int cid = t + it * 256;          // 0..1023
            int arr = cid >> 9;              // 0 K, 1 V
            int rem = cid & 511;
            int row = rem >> 3, ch = rem & 7;
            uint32_t dst = stg + arr * KV_ARR + row * SROW + ch * 16;
            const __half* src = (arr ? Vh : Kh)
                              + (size_t)(kt * 64 + row) * HDdim + ch * 8;
            CPA16(dst, src);
        }
        CPCOMMIT();
    };
    prefetch(0, 0);
    prefetch(1, 1);
    CPWAIT2();               // Q done (kv0/kv1 may still be in flight)
    __syncthreads();

    // Q fragments (persistent): 4 k-chunks
    uint32_t qf[4][4];
    {
        int mrow = wid * 16;
        int aLr = lane & 15, aLc = lane >> 4;
        #pragma unroll
        for (int kc = 0; kc < 4; kc++) {
            uint32_t off = (uint32_t)(mrow + aLr) * SROW + (uint32_t)(kc * 16 + aLc * 8) * 2;
            LDSM4(qf[kc][0], qf[kc][1], qf[kc][2], qf[kc][3], QHs + off);
        }
    }

    float o[8][4];
    #pragma unroll
    for (int i = 0; i < 8; i++)
        #pragma unroll
        for (int j = 0; j < 4; j++) o[i][j] = 0.f;
    float m0r = -1e30f, m1r = -1e30f, l0r = 0.f, l1r = 0.f;

    const int KT = Sdim / 64;    // 32
    for (int kt = 0; kt < KT; kt++) {
        if (kt + 2 < KT) { prefetch(kt + 2, (kt + 2) % 3); CPWAIT2(); }
        else if (kt + 1 < KT) { CPWAIT1(); }
        else { CPWAIT0(); }
        __syncthreads();
        uint32_t stg = KVs + (kt % 3) * KV_STG;
        uint32_t KHb = stg, VHb = stg + KV_ARR;

        // ---- scores ----
        float c[8][4];
        #pragma unroll
        for (int i = 0; i < 8; i++)
            #pragma unroll
            for (int j = 0; j < 4; j++) c[i][j] = 0.f;

        int kRow = (lane & 7);
        int kCol = ((lane >> 3) << 3);
        #pragma unroll
        for (int nt = 0; nt < 8; nt++) {
            uint32_t base = (uint32_t)(nt * 8 + kRow) * SROW + kCol * 2;
            uint32_t khf[8];
            LDSM4(khf[0], khf[1], khf[2], khf[3], KHb + base);
            LDSM4(khf[4], khf[5], khf[6], khf[7], KHb + base + 64);
            #pragma unroll
            for (int kc = 0; kc < 4; kc++)
                MMAF16(c[nt], qf[kc], &khf[kc * 2]);
        }

        // ---- online softmax (base-2) ----
        float m0 = -1e30f, m1 = -1e30f;
        #pragma unroll
        for (int nt = 0; nt < 8; nt++) {
            m0 = fmaxf(m0, fmaxf(c[nt][0], c[nt][1]));
            m1 = fmaxf(m1, fmaxf(c[nt][2], c[nt][3]));
        }
        m0 = fmaxf(m0, __shfl_xor_sync(0xffffffffu, m0, 1));
        m0 = fmaxf(m0, __shfl_xor_sync(0xffffffffu, m0, 2));
        m1 = fmaxf(m1, __shfl_xor_sync(0xffffffffu, m1, 1));
        m1 = fmaxf(m1, __shfl_xor_sync(0xffffffffu, m1, 2));
        float mn0 = fmaxf(m0r, m0), mn1 = fmaxf(m1r, m1);
        float a0 = fexp2(m0r - mn0), a1 = fexp2(m1r - mn1);
        float s0 = 0.f, s1 = 0.f;
        #pragma unroll
        for (int nt = 0; nt < 8; nt++) {
            c[nt][0] = fexp2(c[nt][0] - mn0);
            c[nt][1] = fexp2(c[nt][1] - mn0);
            c[nt][2] = fexp2(c[nt][2] - mn1);
            c[nt][3] = fexp2(c[nt][3] - mn1);
            s0 += c[nt][0] + c[nt][1];
            s1 += c[nt][2] + c[nt][3];
        }
        s0 += __shfl_xor_sync(0xffffffffu, s0, 1);
        s0 += __shfl_xor_sync(0xffffffffu, s0, 2);
        s1 += __shfl_xor_sync(0xffffffffu, s1, 1);
        s1 += __shfl_xor_sync(0xffffffffu, s1, 2);
        l0r = l0r * a0 + s0;
        l1r = l1r * a1 + s1;
        m0r = mn0; m1r = mn1;
        #pragma unroll
        for (int i = 0; i < 8; i++) {
            o[i][0] *= a0; o[i][1] *= a0;
            o[i][2] *= a1; o[i][3] *= a1;
        }

        // ---- P fragments (registers, fp16) ----
        uint32_t ph[4][4];
        #pragma unroll
        for (int kc = 0; kc < 4; kc++) {
            ph[kc][0] = pack2h(__float2half_rn(c[2*kc][0]),   __float2half_rn(c[2*kc][1]));
            ph[kc][1] = pack2h(__float2half_rn(c[2*kc][2]),   __float2half_rn(c[2*kc][3]));
            ph[kc][2] = pack2h(__float2half_rn(c[2*kc+1][0]), __float2half_rn(c[2*kc+1][1]));
            ph[kc][3] = pack2h(__float2half_rn(c[2*kc+1][2]), __float2half_rn(c[2*kc+1][3]));
        }

        // ---- O += P @ V ----
        int vRow = ((lane >> 3) & 1) * 8 + (lane & 7);
        int vCol = ((lane >> 4) << 3);
        #pragma unroll
        for (int np = 0; np < 4; np++) {
            #pragma unroll
            for (int kc = 0; kc < 4; kc++) {
                uint32_t base = (uint32_t)(kc * 16 + vRow) * SROW
                              + (uint32_t)(np * 16 + vCol) * 2;
                uint32_t vhf[4];
                LDSM4T(vhf[0], vhf[1], vhf[2], vhf[3], VHb + base);
                MMAF16(o[2*np],   ph[kc], &vhf[0]);
                MMAF16(o[2*np+1], ph[kc], &vhf[2]);
            }
        }
        __syncthreads();
    }

    // ---- epilogue: divide by l, write fp16 to [B,S,D] ----
    float inv0 = 1.0f / l0r, inv1 = 1.0f / l1r;
    int r0 = q0 + wid * 16 + g, r1 = r0 + 8;
    size_t base0 = ((size_t)b_ * Sdim + r0) * Ddim + h_ * HDdim;
    size_t base1 = ((size_t)b_ * Sdim + r1) * Ddim + h_ * HDdim;
    #pragma unroll
    for (int nt = 0; nt < 8; nt++) {
        int col = nt * 8 + t4 * 2;
        *(uint32_t*)(O + base0 + col) =
            pack2h(__float2half_rn(o[nt][0] * inv0), __float2half_rn(o[nt][1] * inv0));
        *(uint32_t*)(O + base1 + col) =
            pack2h(__float2half_rn(o[nt][2] * inv1), __float2half_rn(o[nt][3] * inv1));
    }
}

// ===========================================================================
// Launch
// ===========================================================================
extern "C" void kernel_launch(void* const* d_in, const int* in_sizes, int n_in,
                              void* d_out, int out_size) {
    const float* x   = (const float*)d_in[0];
    const float* Wq  = (const float*)d_in[1];
    const float* bq  = (const float*)d_in[2];
    const float* Wk  = (const float*)d_in[3];
    const float* bk  = (const float*)d_in[4];
    const float* Wv  = (const float*)d_in[5];
    const float* bv  = (const float*)d_in[6];
    const float* Wo  = (const float*)d_in[7];
    const float* bo  = (const float*)d_in[8];
    const float* W1  = (const float*)d_in[9];
    const float* b1  = (const float*)d_in[10];
    const float* W2  = (const float*)d_in[11];
    const float* b2  = (const float*)d_in[12];
    const float* g1  = (const float*)d_in[13];
    const float* be1 = (const float*)d_in[14];
    const float* g2  = (const float*)d_in[15];
    const float* be2 = (const float*)d_in[16];
    float* out = (float*)d_out;

    float *x1, *b3;
    __half *qkvs, *xn, *att, *xn2, *h;
    __half *wqkv, *wo, *w1, *w2;
    cudaGetSymbolAddress((void**)&x1, g_x1);
    cudaGetSymbolAddress((void**)&b3, g_b3);
    cudaGetSymbolAddress((void**)&qkvs, g_qkvs);
    cudaGetSymbolAddress((void**)&xn, g_xn);
    cudaGetSymbolAddress((void**)&att, g_att);
    cudaGetSymbolAddress((void**)&xn2, g_xn2);
    cudaGetSymbolAddress((void**)&h, g_h);
    cudaGetSymbolAddress((void**)&wqkv, g_wqkv);
    cudaGetSymbolAddress((void**)&wo, g_wo);
    cudaGetSymbolAddress((void**)&w1, g_w1);
    cudaGetSymbolAddress((void**)&w2, g_w2);

    cudaFuncSetAttribute(gemm_tc<0>, cudaFuncAttributeMaxDynamicSharedMemorySize, GEMM_SMEM);
    cudaFuncSetAttribute(gemm_tc<1>, cudaFuncAttributeMaxDynamicSharedMemorySize, GEMM_SMEM);
    cudaFuncSetAttribute(gemm_tc<2>, cudaFuncAttributeMaxDynamicSharedMemorySize, GEMM_SMEM);
    cudaFuncSetAttribute(attn_tc, cudaFuncAttributeMaxDynamicSharedMemorySize, ATTN_SMEM);

    dim3 blk(256);
    prep_all<<<12300, blk>>>(Wq, Wk, Wv, Wo, W1, W2, bq, bk, bv,
                             wqkv, wo, w1, w2, b3);

    ln_h<<<Mdim, blk>>>(x, g1, be1, xn);
    gemm_tc<0><<<dim3(24, 64), blk, GEMM_SMEM>>>(xn, wqkv, b3,
                                                 nullptr, nullptr, qkvs, 3072, Ddim);
    attn_tc<<<dim3(Sdim / 128, Bdim * Hdim), blk, ATTN_SMEM>>>(qkvs, att);
    gemm_tc<1><<<dim3(8, 64), blk, GEMM_SMEM>>>(att, wo, bo,
                                                x, x1, nullptr, Ddim, Ddim);
    ln_h<<<Mdim, blk>>>(x1, g2, be2, xn2);
    gemm_tc<2><<<dim3(32, 64), blk, GEMM_SMEM>>>(xn2, w1, b1,
                                                 nullptr, nullptr, h, Fdim, Ddim);
    gemm_tc<1><<<dim3(8, 64), blk, GEMM_SMEM>>>(h, w2, b2,
                                                x1, out, nullptr, Ddim, Fdim);
}